// round 6
// baseline (speedup 1.0000x reference)
#include <cuda_runtime.h>
#include <math.h>

// Problem constants
#define BB   4
#define LL   2048
#define EE   7
#define DD   512
#define HH   8
#define DH   64
#define PP   720
#define NL   2
#define UU   40
#define BH   (BB*HH)          // 32
#define MROWS (BB*LL)         // 8192
#define SCALE 0.125f          // 1/sqrt(64)

// ---------------- scratch (device globals; no allocation allowed) ----------
__device__ float g_h [BB*LL*DD];
__device__ float g_q [BH*LL*DH];
__device__ float g_k [BH*LL*DH];
__device__ float g_v [BH*LL*DH];
__device__ float g_t1[BB*LL*DD];
__device__ float g_t2[BB*LL*DD];
__device__ float g_M [BH*LL];
__device__ int   g_idx[BH*UU];
__device__ float g_ksum [BH*DH];
__device__ float g_vmean[BH*DH];
__device__ float g_upd[BH*UU*DH];

// ---------------- embedding: h = x @ emb_w + emb_b  (K=7) ------------------
__global__ void embed_kernel(const float* __restrict__ x,
                             const float* __restrict__ w,
                             const float* __restrict__ b,
                             float* __restrict__ out) {
    int i = blockIdx.x * 256 + threadIdx.x;          // over B*L*D
    int row = i >> 9;                                 // b*L + l
    int n   = i & 511;
    float acc = b[n];
    #pragma unroll
    for (int e = 0; e < EE; ++e)
        acc += x[row*EE + e] * w[e*DD + n];
    out[i] = acc;
}

// ---------------- GEMM: [M,512] x [512,512] + bias -------------------------
// MODE 0: plain out[m*512+n];  1: relu;  2: scatter to head layout [B,H,L,DH]
template<int MODE>
__global__ void gemm_dd(const float* __restrict__ A,
                        const float* __restrict__ W,
                        const float* __restrict__ bias,
                        float* __restrict__ out) {
    __shared__ float As[32][65];   // As[k][m], padded
    __shared__ float Bs[32][64];   // Bs[k][n]
    int tx = threadIdx.x, ty = threadIdx.y;
    int tid = ty * 16 + tx;
    int m0 = blockIdx.x * 64, n0 = blockIdx.y * 64;
    float acc[4][4];
    #pragma unroll
    for (int i = 0; i < 4; ++i)
        #pragma unroll
        for (int j = 0; j < 4; ++j) acc[i][j] = 0.f;

    for (int k0 = 0; k0 < 512; k0 += 32) {
        __syncthreads();
        #pragma unroll
        for (int t = 0; t < 8; ++t) {            // A tile 64x32
            int i = tid + t * 256;
            int r = i >> 5, c = i & 31;
            As[c][r] = A[(size_t)(m0 + r) * 512 + k0 + c];
        }
        #pragma unroll
        for (int t = 0; t < 8; ++t) {            // B tile 32x64
            int i = tid + t * 256;
            int r = i >> 6, c = i & 63;
            Bs[r][c] = W[(size_t)(k0 + r) * 512 + n0 + c];
        }
        __syncthreads();
        int mr = ty * 4, nc = tx * 4;
        #pragma unroll
        for (int kk = 0; kk < 32; ++kk) {
            float a0 = As[kk][mr+0], a1 = As[kk][mr+1];
            float a2 = As[kk][mr+2], a3 = As[kk][mr+3];
            float4 bv = *(const float4*)&Bs[kk][nc];
            acc[0][0] += a0*bv.x; acc[0][1] += a0*bv.y; acc[0][2] += a0*bv.z; acc[0][3] += a0*bv.w;
            acc[1][0] += a1*bv.x; acc[1][1] += a1*bv.y; acc[1][2] += a1*bv.z; acc[1][3] += a1*bv.w;
            acc[2][0] += a2*bv.x; acc[2][1] += a2*bv.y; acc[2][2] += a2*bv.z; acc[2][3] += a2*bv.w;
            acc[3][0] += a3*bv.x; acc[3][1] += a3*bv.y; acc[3][2] += a3*bv.z; acc[3][3] += a3*bv.w;
        }
    }
    int mr = m0 + ty * 4, nc = n0 + tx * 4;
    #pragma unroll
    for (int i = 0; i < 4; ++i) {
        int m = mr + i;
        #pragma unroll
        for (int j = 0; j < 4; ++j) {
            int n = nc + j;
            float v = acc[i][j] + bias[n];
            if (MODE == 1) v = fmaxf(v, 0.f);
            if (MODE == 2) {
                int b = m >> 11, l = m & 2047;
                int hh = n >> 6, dh = n & 63;
                out[(((size_t)(b*HH + hh)*LL) + l)*DH + dh] = v;
            } else {
                out[(size_t)m * 512 + n] = v;
            }
        }
    }
}

// ---------------- per-(b,h) sums: ksum, vmean -------------------------------
__global__ void sums_kernel(const float* __restrict__ k,
                            const float* __restrict__ v,
                            float* __restrict__ ksum,
                            float* __restrict__ vmean) {
    int bh = blockIdx.x, d = threadIdx.x;    // 64 threads
    const float* kb = k + (size_t)bh * LL * DH + d;
    const float* vb = v + (size_t)bh * LL * DH + d;
    float ks = 0.f, vs = 0.f;
    for (int l = 0; l < LL; ++l) { ks += kb[(size_t)l*DH]; vs += vb[(size_t)l*DH]; }
    ksum [bh*DH + d] = ks;
    vmean[bh*DH + d] = vs * (1.f / LL);
}

// ---------------- M(q) = SCALE*(max_k q·k - q·ksum/L) -----------------------
__global__ void m_kernel(const float* __restrict__ q,
                         const float* __restrict__ k,
                         const float* __restrict__ ksum,
                         float* __restrict__ Mout) {
    int bh = blockIdx.y;
    int q0 = blockIdx.x * 64;
    const float* qb = q + (size_t)bh * LL * DH;
    const float* kb = k + (size_t)bh * LL * DH;
    __shared__ float Qs[64][65];
    __shared__ float Ks[64][65];
    __shared__ float red[64][17];
    int tx = threadIdx.x, ty = threadIdx.y;
    int tid = ty * 16 + tx;

    #pragma unroll
    for (int t = 0; t < 16; ++t) {
        int i = tid + t * 256;
        int r = i >> 6, c = i & 63;
        Qs[r][c] = qb[(size_t)(q0 + r) * DH + c];
    }
    float rmax[4] = {-INFINITY, -INFINITY, -INFINITY, -INFINITY};

    for (int kt = 0; kt < LL / 64; ++kt) {
        __syncthreads();
        #pragma unroll
        for (int t = 0; t < 16; ++t) {
            int i = tid + t * 256;
            int r = i >> 6, c = i & 63;
            Ks[r][c] = kb[(size_t)(kt * 64 + r) * DH + c];
        }
        __syncthreads();
        float acc[4][4];
        #pragma unroll
        for (int i = 0; i < 4; ++i)
            #pragma unroll
            for (int j = 0; j < 4; ++j) acc[i][j] = 0.f;
        int qr = ty * 4, kc = tx * 4;
        #pragma unroll
        for (int d = 0; d < 64; ++d) {
            float a0 = Qs[qr+0][d], a1 = Qs[qr+1][d], a2 = Qs[qr+2][d], a3 = Qs[qr+3][d];
            float b0 = Ks[kc+0][d], b1 = Ks[kc+1][d], b2 = Ks[kc+2][d], b3 = Ks[kc+3][d];
            acc[0][0]+=a0*b0; acc[0][1]+=a0*b1; acc[0][2]+=a0*b2; acc[0][3]+=a0*b3;
            acc[1][0]+=a1*b0; acc[1][1]+=a1*b1; acc[1][2]+=a1*b2; acc[1][3]+=a1*b3;
            acc[2][0]+=a2*b0; acc[2][1]+=a2*b1; acc[2][2]+=a2*b2; acc[2][3]+=a2*b3;
            acc[3][0]+=a3*b0; acc[3][1]+=a3*b1; acc[3][2]+=a3*b2; acc[3][3]+=a3*b3;
        }
        #pragma unroll
        for (int i = 0; i < 4; ++i) {
            float m = fmaxf(fmaxf(acc[i][0], acc[i][1]), fmaxf(acc[i][2], acc[i][3]));
            rmax[i] = fmaxf(rmax[i], m);
        }
    }
    #pragma unroll
    for (int i = 0; i < 4; ++i) red[ty*4 + i][tx] = rmax[i];
    __syncthreads();
    if (tid < 64) {
        float m = red[tid][0];
        #pragma unroll
        for (int t = 1; t < 16; ++t) m = fmaxf(m, red[tid][t]);
        const float* qrow = qb + (size_t)(q0 + tid) * DH;
        const float* ks = ksum + bh * DH;
        float dot = 0.f;
        #pragma unroll
        for (int d = 0; d < DH; ++d) dot += qrow[d] * ks[d];
        Mout[bh*LL + q0 + tid] = (m - dot * (1.f / LL)) * SCALE;
    }
}

// ---------------- top-U selection per (b,h) --------------------------------
__global__ void topk_kernel(const float* __restrict__ M, int* __restrict__ idxout) {
    int bh = blockIdx.x, tid = threadIdx.x;     // 256 threads
    __shared__ float sm[LL];
    __shared__ float bv[256];
    __shared__ int   bi[256];
    for (int l = tid; l < LL; l += 256) sm[l] = M[bh*LL + l];
    __syncthreads();
    for (int it = 0; it < UU; ++it) {
        float best = -INFINITY; int bidx = LL;
        for (int l = tid; l < LL; l += 256) {
            float v = sm[l];
            if (v > best || (v == best && l < bidx)) { best = v; bidx = l; }
        }
        bv[tid] = best; bi[tid] = bidx;
        __syncthreads();
        for (int s = 128; s > 0; s >>= 1) {
            if (tid < s) {
                if (bv[tid+s] > bv[tid] || (bv[tid+s] == bv[tid] && bi[tid+s] < bi[tid])) {
                    bv[tid] = bv[tid+s]; bi[tid] = bi[tid+s];
                }
            }
            __syncthreads();
        }
        if (tid == 0) { idxout[bh*UU + it] = bi[0]; sm[bi[0]] = -INFINITY; }
        __syncthreads();
    }
}

// ---------------- attention for the U active queries -----------------------
__global__ void attn_kernel(const float* __restrict__ q,
                            const float* __restrict__ k,
                            const float* __restrict__ v,
                            const int* __restrict__ idx,
                            float* __restrict__ upd) {
    int bh = blockIdx.x, u = blockIdx.y;
    int tid = threadIdx.x;                     // 256
    __shared__ float sc[LL];
    __shared__ float qv[DH];
    __shared__ float red4[4][DH];
    __shared__ float rbuf[8];
    __shared__ float sh_m, sh_inv;

    int lq = idx[bh*UU + u];
    if (tid < DH) qv[tid] = q[((size_t)bh*LL + lq)*DH + tid];
    __syncthreads();

    const float4* q4 = (const float4*)qv;
    for (int l = tid; l < LL; l += 256) {
        const float4* kr = (const float4*)(k + ((size_t)bh*LL + l)*DH);
        float d = 0.f;
        #pragma unroll
        for (int t = 0; t < 16; ++t) {
            float4 kv = kr[t], qq = q4[t];
            d += kv.x*qq.x + kv.y*qq.y + kv.z*qq.z + kv.w*qq.w;
        }
        sc[l] = d * SCALE;
    }
    __syncthreads();

    // block max
    float m = -INFINITY;
    for (int l = tid; l < LL; l += 256) m = fmaxf(m, sc[l]);
    for (int o = 16; o > 0; o >>= 1) m = fmaxf(m, __shfl_down_sync(0xffffffffu, m, o));
    if ((tid & 31) == 0) rbuf[tid >> 5] = m;
    __syncthreads();
    if (tid == 0) {
        float t = rbuf[0];
        #pragma unroll
        for (int i = 1; i < 8; ++i) t = fmaxf(t, rbuf[i]);
        sh_m = t;
    }
    __syncthreads();
    float mx = sh_m;

    // exp + sum
    float s = 0.f;
    for (int l = tid; l < LL; l += 256) { float e = expf(sc[l] - mx); sc[l] = e; s += e; }
    for (int o = 16; o > 0; o >>= 1) s += __shfl_down_sync(0xffffffffu, s, o);
    if ((tid & 31) == 0) rbuf[tid >> 5] = s;
    __syncthreads();
    if (tid == 0) {
        float t = 0.f;
        #pragma unroll
        for (int i = 0; i < 8; ++i) t += rbuf[i];
        sh_inv = 1.f / t;
    }
    __syncthreads();

    // weighted sum of V
    int d = tid & 63, lc = tid >> 6;
    float acc = 0.f;
    for (int l = lc; l < LL; l += 4)
        acc += sc[l] * v[((size_t)bh*LL + l)*DH + d];
    red4[lc][d] = acc;
    __syncthreads();
    if (tid < DH) {
        float tot = red4[0][tid] + red4[1][tid] + red4[2][tid] + red4[3][tid];
        upd[((size_t)bh*UU + u)*DH + tid] = tot * sh_inv;
    }
}

// ---------------- context = broadcast vmean, then scatter upd ---------------
__global__ void fill_kernel(const float* __restrict__ vmean, float* __restrict__ ctx) {
    int i = blockIdx.x * 256 + threadIdx.x;     // B*L*D
    int col = i & 511;
    int b = i / (LL * DD);
    int hh = col >> 6, dh = col & 63;
    ctx[i] = vmean[(b*HH + hh)*DH + dh];
}

__global__ void scatter_kernel(const float* __restrict__ upd,
                               const int* __restrict__ idx,
                               float* __restrict__ ctx) {
    int t = blockIdx.x * 256 + threadIdx.x;     // B*H*U*DH = 81920
    int dh = t & 63;
    int u  = (t >> 6) % UU;
    int hh = (t / (64*UU)) % HH;
    int b  = t / (64*UU*HH);
    int l = idx[(b*HH + hh)*UU + u];
    ctx[((size_t)b*LL + l)*DD + hh*DH + dh] = upd[(((size_t)(b*HH + hh))*UU + u)*DH + dh];
}

// ---------------- residual + LayerNorm (in place on h) ----------------------
__global__ void addln_kernel(float* h, const float* __restrict__ a,
                             const float* __restrict__ g, const float* __restrict__ b) {
    int row = blockIdx.x, tid = threadIdx.x;    // 256 threads, D=512
    float* hr = h + (size_t)row * DD;
    const float* ar = a + (size_t)row * DD;
    __shared__ float rbuf[8];
    __shared__ float sh_mean, sh_var;
    float s0 = hr[tid]       + ar[tid];
    float s1 = hr[tid + 256] + ar[tid + 256];
    float s = s0 + s1;
    for (int o = 16; o > 0; o >>= 1) s += __shfl_down_sync(0xffffffffu, s, o);
    if ((tid & 31) == 0) rbuf[tid >> 5] = s;
    __syncthreads();
    if (tid == 0) {
        float t = 0.f;
        #pragma unroll
        for (int i = 0; i < 8; ++i) t += rbuf[i];
        sh_mean = t * (1.f / DD);
    }
    __syncthreads();
    float mval = sh_mean;
    float d0 = s0 - mval, d1 = s1 - mval;
    float vv = d0*d0 + d1*d1;
    for (int o = 16; o > 0; o >>= 1) vv += __shfl_down_sync(0xffffffffu, vv, o);
    if ((tid & 31) == 0) rbuf[tid >> 5] = vv;
    __syncthreads();
    if (tid == 0) {
        float t = 0.f;
        #pragma unroll
        for (int i = 0; i < 8; ++i) t += rbuf[i];
        sh_var = t * (1.f / DD);
    }
    __syncthreads();
    float inv = rsqrtf(sh_var + 1e-5f);
    hr[tid]       = d0 * inv * g[tid]       + b[tid];
    hr[tid + 256] = d1 * inv * g[tid + 256] + b[tid + 256];
}

// ---------------- final projection: h[:, -P:, :] @ proj_w + proj_b ----------
__global__ void proj_kernel(const float* __restrict__ h,
                            const float* __restrict__ pw,
                            const float* __restrict__ pb,
                            float* __restrict__ out) {
    int bp = blockIdx.x;                       // B*P
    int b = bp / PP, p = bp % PP;
    int l = LL - PP + p;
    int tid = threadIdx.x;                     // 64
    const float* hr = h + ((size_t)b*LL + l)*DD;
    float acc[EE];
    #pragma unroll
    for (int e = 0; e < EE; ++e) acc[e] = 0.f;
    for (int kk = tid; kk < DD; kk += 64) {
        float hv = hr[kk];
        #pragma unroll
        for (int e = 0; e < EE; ++e) acc[e] += hv * pw[kk*EE + e];
    }
    __shared__ float red[EE][64];
    #pragma unroll
    for (int e = 0; e < EE; ++e) red[e][tid] = acc[e];
    __syncthreads();
    if (tid < EE) {
        float t = 0.f;
        for (int i = 0; i < 64; ++i) t += red[tid][i];
        out[(size_t)bp * EE + tid] = t + pb[tid];
    }
}

// ---------------- host driver ----------------------------------------------
extern "C" void kernel_launch(void* const* d_in, const int* in_sizes, int n_in,
                              void* d_out, int out_size) {
    const float* x      = (const float*)d_in[0];
    const float* emb_w  = (const float*)d_in[1];
    const float* emb_b  = (const float*)d_in[2];
    const float* Wq     = (const float*)d_in[3];
    const float* bq     = (const float*)d_in[4];
    const float* Wk     = (const float*)d_in[5];
    const float* bk     = (const float*)d_in[6];
    const float* Wv     = (const float*)d_in[7];
    const float* bv     = (const float*)d_in[8];
    const float* Wo     = (const float*)d_in[9];
    const float* bo     = (const float*)d_in[10];
    const float* W1     = (const float*)d_in[11];
    const float* b1     = (const float*)d_in[12];
    const float* W2     = (const float*)d_in[13];
    const float* b2     = (const float*)d_in[14];
    const float* ln1_g  = (const float*)d_in[15];
    const float* ln1_b  = (const float*)d_in[16];
    const float* ln2_g  = (const float*)d_in[17];
    const float* ln2_b  = (const float*)d_in[18];
    const float* proj_w = (const float*)d_in[19];
    const float* proj_b = (const float*)d_in[20];

    static float *p_h = nullptr, *p_q, *p_k, *p_v, *p_t1, *p_t2, *p_M,
                 *p_ksum, *p_vmean, *p_upd;
    static int *p_idx;
    if (!p_h) {
        cudaGetSymbolAddress((void**)&p_h,    g_h);
        cudaGetSymbolAddress((void**)&p_q,    g_q);
        cudaGetSymbolAddress((void**)&p_k,    g_k);
        cudaGetSymbolAddress((void**)&p_v,    g_v);
        cudaGetSymbolAddress((void**)&p_t1,   g_t1);
        cudaGetSymbolAddress((void**)&p_t2,   g_t2);
        cudaGetSymbolAddress((void**)&p_M,    g_M);
        cudaGetSymbolAddress((void**)&p_idx,  g_idx);
        cudaGetSymbolAddress((void**)&p_ksum, g_ksum);
        cudaGetSymbolAddress((void**)&p_vmean,g_vmean);
        cudaGetSymbolAddress((void**)&p_upd,  g_upd);
    }

    embed_kernel<<<(BB*LL*DD)/256, 256>>>(x, emb_w, emb_b, p_h);

    dim3 gg(MROWS/64, DD/64), bb(16, 16);
    for (int il = 0; il < NL; ++il) {
        const size_t wo = (size_t)il * DD * DD;
        const size_t bo_off = (size_t)il * DD;
        gemm_dd<2><<<gg, bb>>>(p_h, Wq + wo, bq + bo_off, p_q);
        gemm_dd<2><<<gg, bb>>>(p_h, Wk + wo, bk + bo_off, p_k);
        gemm_dd<2><<<gg, bb>>>(p_h, Wv + wo, bv + bo_off, p_v);
        sums_kernel<<<BH, DH>>>(p_k, p_v, p_ksum, p_vmean);
        m_kernel<<<dim3(LL/64, BH), bb>>>(p_q, p_k, p_ksum, p_M);
        topk_kernel<<<BH, 256>>>(p_M, p_idx);
        attn_kernel<<<dim3(BH, UU), 256>>>(p_q, p_k, p_v, p_idx, p_upd);
        fill_kernel<<<(BB*LL*DD)/256, 256>>>(p_vmean, p_t1);
        scatter_kernel<<<(BH*UU*DH)/256, 256>>>(p_upd, p_idx, p_t1);
        gemm_dd<0><<<gg, bb>>>(p_t1, Wo + wo, bo + bo_off, p_t2);
        addln_kernel<<<MROWS, 256>>>(p_h, p_t2, ln1_g + bo_off, ln1_b + bo_off);
        gemm_dd<1><<<gg, bb>>>(p_h, W1 + wo, b1 + bo_off, p_t1);
        gemm_dd<0><<<gg, bb>>>(p_t1, W2 + wo, b2 + bo_off, p_t2);
        addln_kernel<<<MROWS, 256>>>(p_h, p_t2, ln2_g + bo_off, ln2_b + bo_off);
    }

    proj_kernel<<<BB*PP, 64>>>(p_h, proj_w, proj_b, (float*)d_out);
}

// round 8
// speedup vs baseline: 1.2697x; 1.2697x over previous
#include <cuda_runtime.h>
#include <math.h>

#define BB   4
#define LL   2048
#define EE   7
#define DD   512
#define HH   8
#define DH   64
#define PP   720
#define NL   2
#define UU   40
#define BH   (BB*HH)          // 32
#define MROWS (BB*LL)         // 8192
#define SCALE 0.125f

typedef unsigned long long ull;

__device__ __forceinline__ void ffma2(ull &d, ull a, ull b) {
    asm("fma.rn.f32x2 %0, %1, %2, %0;" : "+l"(d) : "l"(a), "l"(b));
}
__device__ __forceinline__ ull pack2(float x, float y) {
    ull r; asm("mov.b64 %0, {%1, %2};" : "=l"(r) : "f"(x), "f"(y)); return r;
}
__device__ __forceinline__ float2 unpack2(ull p) {
    float2 r; asm("mov.b64 {%0, %1}, %2;" : "=f"(r.x), "=f"(r.y) : "l"(p)); return r;
}

// ---------------- scratch ---------------------------------------------------
__device__ float g_h [BB*LL*DD];
__device__ float g_q [BH*LL*DH];
__device__ float g_k [BH*LL*DH];
__device__ float g_v [BH*LL*DH];
__device__ float g_t1[BB*LL*DD];
__device__ float g_t2[BB*LL*DD];
__device__ float g_M [BH*LL];
__device__ int   g_idx[BH*UU];
__device__ float g_ksum [BH*DH];
__device__ float g_vmean[BH*DH];
__device__ float g_upd[BH*UU*DH];
__device__ float g_base[BB*DD];

// ---------------- embedding -------------------------------------------------
__global__ void embed_kernel(const float* __restrict__ x,
                             const float* __restrict__ w,
                             const float* __restrict__ b,
                             float* __restrict__ out) {
    int i = blockIdx.x * 256 + threadIdx.x;
    int row = i >> 9;
    int n   = i & 511;
    float acc = b[n];
    #pragma unroll
    for (int e = 0; e < EE; ++e)
        acc += x[row*EE + e] * w[e*DD + n];
    out[i] = acc;
}

// ---------------- GEMM [8192,512]x[512,512]+bias, f32x2 ---------------------
// MODE 0: plain; 1: relu; 2: scatter to head layout [B,H,L,DH]
template<int MODE>
__global__ __launch_bounds__(256, 2)
void gemm_dd(const float* __restrict__ A, const float* __restrict__ W,
             const float* __restrict__ bias, float* __restrict__ out) {
    __shared__ float As[128][32];
    __shared__ float Bs[32][132];
    const int tid = threadIdx.x;
    const int tx = tid & 15, ty = tid >> 4;
    const int m0 = blockIdx.x * 128, n0 = blockIdx.y * 128;
    ull acc[8][4];
    #pragma unroll
    for (int i = 0; i < 8; ++i)
        #pragma unroll
        for (int j = 0; j < 4; ++j) acc[i][j] = 0ull;

    for (int k0 = 0; k0 < 512; k0 += 32) {
        __syncthreads();
        #pragma unroll
        for (int t = 0; t < 4; ++t) {                // A: 128x32
            int i = tid + t * 256;
            int r = i >> 3, c = (i & 7) * 4;
            *(float4*)&As[r][c] = *(const float4*)&A[(size_t)(m0 + r)*512 + k0 + c];
        }
        #pragma unroll
        for (int t = 0; t < 4; ++t) {                // B: 32x128
            int i = tid + t * 256;
            int r = i >> 5, c = (i & 31) * 4;
            *(float4*)&Bs[r][c] = *(const float4*)&W[(size_t)(k0 + r)*512 + n0 + c];
        }
        __syncthreads();
        #pragma unroll 4
        for (int kk = 0; kk < 32; ++kk) {
            ull bfr[4];
            #pragma unroll
            for (int j = 0; j < 4; ++j)
                bfr[j] = *(const ull*)&Bs[kk][j*32 + tx*2];
            #pragma unroll
            for (int i = 0; i < 8; ++i) {
                float av = As[ty*8 + i][kk];
                ull aa = pack2(av, av);
                #pragma unroll
                for (int j = 0; j < 4; ++j) ffma2(acc[i][j], aa, bfr[j]);
            }
        }
    }
    #pragma unroll
    for (int i = 0; i < 8; ++i) {
        int m = m0 + ty*8 + i;
        int b_ = m >> 11, l_ = m & 2047;
        #pragma unroll
        for (int j = 0; j < 4; ++j) {
            int n = n0 + j*32 + tx*2;
            float2 v = unpack2(acc[i][j]);
            float2 b2 = *(const float2*)&bias[n];
            v.x += b2.x; v.y += b2.y;
            if (MODE == 1) { v.x = fmaxf(v.x, 0.f); v.y = fmaxf(v.y, 0.f); }
            if (MODE == 2) {
                int hh = n >> 6, dh = n & 63;
                *(float2*)&out[(((size_t)(b_*HH + hh))*LL + l_)*DH + dh] = v;
            } else {
                *(float2*)&out[(size_t)m*512 + n] = v;
            }
        }
    }
}

// ---------------- per-(b,h) sums --------------------------------------------
__global__ void sums_kernel(const float* __restrict__ k,
                            const float* __restrict__ v,
                            float* __restrict__ ksum,
                            float* __restrict__ vmean) {
    int bh = blockIdx.x, tid = threadIdx.x;   // 256
    int d = tid & 63, c = tid >> 6;
    const float* kb = k + (size_t)bh * LL * DH + d;
    const float* vb = v + (size_t)bh * LL * DH + d;
    float ks = 0.f, vs = 0.f;
    for (int l = c; l < LL; l += 4) { ks += kb[(size_t)l*DH]; vs += vb[(size_t)l*DH]; }
    __shared__ float rk[4][64], rv[4][64];
    rk[c][d] = ks; rv[c][d] = vs;
    __syncthreads();
    if (tid < 64) {
        float a = rk[0][tid] + rk[1][tid] + rk[2][tid] + rk[3][tid];
        float m = rv[0][tid] + rv[1][tid] + rv[2][tid] + rv[3][tid];
        ksum [bh*DH + tid] = a;
        vmean[bh*DH + tid] = m * (1.f / LL);
    }
}

// ---------------- M(q) via 128x128 f32x2 score tiles ------------------------
__global__ __launch_bounds__(256, 2)
void m_kernel(const float* __restrict__ q, const float* __restrict__ k,
              const float* __restrict__ ksum, float* __restrict__ Mout) {
    extern __shared__ float sm[];
    float (*Qs)[64]  = (float(*)[64])sm;                 // 128x64
    float (*Ks)[132] = (float(*)[132])(sm + 128*64);     // 64x132
    float* red = sm + 128*64 + 64*132;                   // 128
    int bh = blockIdx.y, q0 = blockIdx.x * 128;
    const float* qb = q + (size_t)bh * LL * DH;
    const float* kb = k + (size_t)bh * LL * DH;
    int tid = threadIdx.x;
    int tx = tid & 15, ty = tid >> 4;

    #pragma unroll
    for (int t = 0; t < 8; ++t) {                        // Q: coalesced, row-major
        int i = tid + t * 256;
        int r = i >> 4, c = (i & 15) * 4;
        *(float4*)&Qs[r][c] = *(const float4*)&qb[(size_t)(q0 + r)*DH + c];
    }
    float rmax[8];
    #pragma unroll
    for (int i = 0; i < 8; ++i) rmax[i] = -INFINITY;

    for (int kt = 0; kt < LL/128; ++kt) {
        __syncthreads();
        #pragma unroll
        for (int t = 0; t < 8; ++t) {                    // K: transposed into smem
            int i = tid + t * 256;
            int r = i & 127, c = (i >> 7) * 4;
            float4 kv = *(const float4*)&kb[(size_t)(kt*128 + r)*DH + c];
            Ks[c+0][r] = kv.x; Ks[c+1][r] = kv.y; Ks[c+2][r] = kv.z; Ks[c+3][r] = kv.w;
        }
        __syncthreads();
        ull acc[8][4];
        #pragma unroll
        for (int i = 0; i < 8; ++i)
            #pragma unroll
            for (int j = 0; j < 4; ++j) acc[i][j] = 0ull;
        #pragma unroll 4
        for (int d = 0; d < 64; ++d) {
            ull bfr[4];
            #pragma unroll
            for (int j = 0; j < 4; ++j)
                bfr[j] = *(const ull*)&Ks[d][j*32 + tx*2];
            #pragma unroll
            for (int i = 0; i < 8; ++i) {
                float av = Qs[ty*8 + i][d];
                ull aa = pack2(av, av);
                #pragma unroll
                for (int j = 0; j < 4; ++j) ffma2(acc[i][j], aa, bfr[j]);
            }
        }
        #pragma unroll
        for (int i = 0; i < 8; ++i)
            #pragma unroll
            for (int j = 0; j < 4; ++j) {
                float2 v = unpack2(acc[i][j]);
                rmax[i] = fmaxf(rmax[i], fmaxf(v.x, v.y));
            }
    }
    #pragma unroll
    for (int i = 0; i < 8; ++i) {
        #pragma unroll
        for (int o = 1; o < 16; o <<= 1)
            rmax[i] = fmaxf(rmax[i], __shfl_xor_sync(0xffffffffu, rmax[i], o));
    }
    if (tx == 0) {
        #pragma unroll
        for (int i = 0; i < 8; ++i) red[ty*8 + i] = rmax[i];
    }
    __syncthreads();
    if (tid < 128) {
        const float* ks = ksum + bh * DH;
        float dot = 0.f;
        #pragma unroll
        for (int dd = 0; dd < 64; ++dd) {
            int d = (dd + tid) & 63;                     // rotate: conflict-free smem
            dot += Qs[tid][d] * ks[d];
        }
        Mout[bh*LL + q0 + tid] = (red[tid] - dot * (1.f / LL)) * SCALE;
    }
}

// ---------------- top-U selection per (b,h) ---------------------------------
__global__ void topk_kernel(const float* __restrict__ M, int* __restrict__ idxout) {
    int bh = blockIdx.x, tid = threadIdx.x;
    __shared__ float sm[LL];
    __shared__ float bv[256];
    __shared__ int   bi[256];
    for (int l = tid; l < LL; l += 256) sm[l] = M[bh*LL + l];
    __syncthreads();
    for (int it = 0; it < UU; ++it) {
        float best = -INFINITY; int bidx = LL;
        for (int l = tid; l < LL; l += 256) {
            float v = sm[l];
            if (v > best || (v == best && l < bidx)) { best = v; bidx = l; }
        }
        bv[tid] = best; bi[tid] = bidx;
        __syncthreads();
        for (int s = 128; s > 0; s >>= 1) {
            if (tid < s) {
                if (bv[tid+s] > bv[tid] || (bv[tid+s] == bv[tid] && bi[tid+s] < bi[tid])) {
                    bv[tid] = bv[tid+s]; bi[tid] = bi[tid+s];
                }
            }
            __syncthreads();
        }
        if (tid == 0) { idxout[bh*UU + it] = bi[0]; sm[bi[0]] = -INFINITY; }
        __syncthreads();
    }
}

// ---------------- attention: 8 active queries per block ---------------------
__global__ __launch_bounds__(256, 2)
void attn_kernel(const float* __restrict__ q, const float* __restrict__ k,
                 const float* __restrict__ v, const int* __restrict__ idx,
                 float* __restrict__ upd) {
    extern __shared__ float sb[];
    float* sc   = sb;                  // 8*2048
    float* qv   = sb + 8*2048;         // 8*64
    float* red  = qv + 512;            // 4*8*64
    float* sinv = red + 2048;          // 8
    int bh = blockIdx.x, u0 = blockIdx.y * 8;
    int tid = threadIdx.x;
    const float* kb = k + (size_t)bh * LL * DH;
    const float* vb = v + (size_t)bh * LL * DH;

    for (int i = tid; i < 8*64; i += 256) {
        int u = i >> 6, d = i & 63;
        int lq = idx[bh*UU + u0 + u];
        qv[i] = q[((size_t)bh*LL + lq)*DH + d];
    }
    __syncthreads();

    for (int l = tid; l < LL; l += 256) {
        const float4* kr = (const float4*)(kb + (size_t)l*DH);
        float acc[8];
        #pragma unroll
        for (int u = 0; u < 8; ++u) acc[u] = 0.f;
        #pragma unroll
        for (int t = 0; t < 16; ++t) {
            float4 kv = kr[t];
            #pragma unroll
            for (int u = 0; u < 8; ++u) {
                float4 qq = *(const float4*)&qv[u*64 + t*4];
                acc[u] += kv.x*qq.x + kv.y*qq.y + kv.z*qq.z + kv.w*qq.w;
            }
        }
        #pragma unroll
        for (int u = 0; u < 8; ++u) sc[u*2048 + l] = acc[u] * SCALE;
    }
    __syncthreads();

    {   // per-warp softmax (warp u handles query u)
        int u = tid >> 5, lane = tid & 31;
        float m = -INFINITY;
        for (int l = lane; l < LL; l += 32) m = fmaxf(m, sc[u*2048 + l]);
        #pragma unroll
        for (int o = 16; o > 0; o >>= 1) m = fmaxf(m, __shfl_xor_sync(0xffffffffu, m, o));
        float s = 0.f;
        for (int l = lane; l < LL; l += 32) {
            float e = __expf(sc[u*2048 + l] - m);
            sc[u*2048 + l] = e; s += e;
        }
        #pragma unroll
        for (int o = 16; o > 0; o >>= 1) s += __shfl_xor_sync(0xffffffffu, s, o);
        if (lane == 0) sinv[u] = 1.f / s;
    }
    __syncthreads();

    int d = tid & 63, lc = tid >> 6;
    float acc[8];
    #pragma unroll
    for (int u = 0; u < 8; ++u) acc[u] = 0.f;
    for (int l = lc; l < LL; l += 4) {
        float vv = vb[(size_t)l*DH + d];
        #pragma unroll
        for (int u = 0; u < 8; ++u) acc[u] += sc[u*2048 + l] * vv;
    }
    #pragma unroll
    for (int u = 0; u < 8; ++u) red[(lc*8 + u)*64 + d] = acc[u];
    __syncthreads();
    if (tid < 64) {
        #pragma unroll
        for (int u = 0; u < 8; ++u) {
            float t = red[u*64 + tid] + red[(8+u)*64 + tid] +
                      red[(16+u)*64 + tid] + red[(24+u)*64 + tid];
            upd[((size_t)bh*UU + u0 + u)*DH + tid] = t * sinv[u];
        }
    }
}

// ---------------- base = vmeanCat @ Wo + bo  (4 rows) -----------------------
__global__ void base_kernel(const float* __restrict__ vmean,
                            const float* __restrict__ Wo,
                            const float* __restrict__ bo,
                            float* __restrict__ base) {
    int b = blockIdx.x, n = threadIdx.x;        // 512 threads
    const float* vm = vmean + b * 512;          // [h*64+d] ordering == D cols
    float acc = bo[n];
    for (int kk = 0; kk < 512; ++kk)
        acc += vm[kk] * Wo[(size_t)kk*512 + n];
    base[b*512 + n] = acc;
}

// ---------------- sparse corrections: (upd - vmean_h) @ Wo_h ----------------
__global__ void corr_kernel(const float* __restrict__ upd,
                            const float* __restrict__ vmean,
                            const float* __restrict__ Wo,
                            const int* __restrict__ idx,
                            float* __restrict__ delta) {
    int blk = blockIdx.x;                       // bh*UU + u
    int bh = blk / UU, u = blk % UU;
    int h = bh & 7, b = bh >> 3;
    __shared__ float du[64];
    int tid = threadIdx.x;                      // 256
    if (tid < 64) du[tid] = upd[(size_t)blk*64 + tid] - vmean[bh*64 + tid];
    __syncthreads();
    int l = idx[bh*UU + u];
    float* drow = delta + ((size_t)b*LL + l)*DD;
    const float* wrow = Wo + (size_t)h*64*512;
    #pragma unroll
    for (int half = 0; half < 2; ++half) {
        int n = tid + half*256;
        float acc = 0.f;
        #pragma unroll 8
        for (int d = 0; d < 64; ++d) acc += du[d] * wrow[(size_t)d*512 + n];
        atomicAdd(&drow[n], acc);
    }
}

// ---------------- residual + LayerNorm variants -----------------------------
__global__ void addln_base_kernel(float* h, const float* __restrict__ delta,
                                  const float* __restrict__ base,
                                  const float* __restrict__ g, const float* __restrict__ b) {
    int row = blockIdx.x, tid = threadIdx.x;    // 256
    int bb_ = row >> 11;
    float* hr = h + (size_t)row * DD;
    const float* dr = delta + (size_t)row * DD;
    const float* br = base + bb_ * DD;
    __shared__ float rbuf[8];
    __shared__ float sh_mean, sh_var;
    float s0 = hr[tid]       + dr[tid]       + br[tid];
    float s1 = hr[tid + 256] + dr[tid + 256] + br[tid + 256];
    float s = s0 + s1;
    for (int o = 16; o > 0; o >>= 1) s += __shfl_down_sync(0xffffffffu, s, o);
    if ((tid & 31) == 0) rbuf[tid >> 5] = s;
    __syncthreads();
    if (tid == 0) {
        float t = 0.f;
        #pragma unroll
        for (int i = 0; i < 8; ++i) t += rbuf[i];
        sh_mean = t * (1.f / DD);
    }
    __syncthreads();
    float mval = sh_mean;
    float d0 = s0 - mval, d1 = s1 - mval;
    float vv = d0*d0 + d1*d1;
    for (int o = 16; o > 0; o >>= 1) vv += __shfl_down_sync(0xffffffffu, vv, o);
    if ((tid & 31) == 0) rbuf[tid >> 5] = vv;
    __syncthreads();
    if (tid == 0) {
        float t = 0.f;
        #pragma unroll
        for (int i = 0; i < 8; ++i) t += rbuf[i];
        sh_var = t * (1.f / DD);
    }
    __syncthreads();
    float inv = rsqrtf(sh_var + 1e-5f);
    hr[tid]       = d0 * inv * g[tid]       + b[tid];
    hr[tid + 256] = d1 * inv * g[tid + 256] + b[tid + 256];
}

__global__ void addln_kernel(float* h, const float* __restrict__ a,
                             const float* __restrict__ g, const float* __restrict__ b) {
    int row = blockIdx.x, tid = threadIdx.x;
    float* hr = h + (size_t)row * DD;
    const float* ar = a + (size_t)row * DD;
    __shared__ float rbuf[8];
    __shared__ float sh_mean, sh_var;
    float s0 = hr[tid]       + ar[tid];
    float s1 = hr[tid + 256] + ar[tid + 256];
    float s = s0 + s1;
    for (int o = 16; o > 0; o >>= 1) s += __shfl_down_sync(0xffffffffu, s, o);
    if ((tid & 31) == 0) rbuf[tid >> 5] = s;
    __syncthreads();
    if (tid == 0) {
        float t = 0.f;
        #pragma unroll
        for (int i = 0; i < 8; ++i) t += rbuf[i];
        sh_mean = t * (1.f / DD);
    }
    __syncthreads();
    float mval = sh_mean;
    float d0 = s0 - mval, d1 = s1 - mval;
    float vv = d0*d0 + d1*d1;
    for (int o = 16; o > 0; o >>= 1) vv += __shfl_down_sync(0xffffffffu, vv, o);
    if ((tid & 31) == 0) rbuf[tid >> 5] = vv;
    __syncthreads();
    if (tid == 0) {
        float t = 0.f;
        #pragma unroll
        for (int i = 0; i < 8; ++i) t += rbuf[i];
        sh_var = t * (1.f / DD);
    }
    __syncthreads();
    float inv = rsqrtf(sh_var + 1e-5f);
    hr[tid]       = d0 * inv * g[tid]       + b[tid];
    hr[tid + 256] = d1 * inv * g[tid + 256] + b[tid + 256];
}

// ---------------- final projection ------------------------------------------
__global__ void proj_kernel(const float* __restrict__ h,
                            const float* __restrict__ pw,
                            const float* __restrict__ pb,
                            float* __restrict__ out) {
    int bp = blockIdx.x;
    int b = bp / PP, p = bp % PP;
    int l = LL - PP + p;
    int tid = threadIdx.x;                     // 64
    const float* hr = h + ((size_t)b*LL + l)*DD;
    float acc[EE];
    #pragma unroll
    for (int e = 0; e < EE; ++e) acc[e] = 0.f;
    for (int kk = tid; kk < DD; kk += 64) {
        float hv = hr[kk];
        #pragma unroll
        for (int e = 0; e < EE; ++e) acc[e] += hv * pw[kk*EE + e];
    }
    __shared__ float red[EE][64];
    #pragma unroll
    for (int e = 0; e < EE; ++e) red[e][tid] = acc[e];
    __syncthreads();
    if (tid < EE) {
        float t = 0.f;
        for (int i = 0; i < 64; ++i) t += red[tid][i];
        out[(size_t)bp * EE + tid] = t + pb[tid];
    }
}

// ---------------- host driver ------------------------------------------------
#define SMEM_M_BYTES ((128*64 + 64*132 + 128) * 4)
#define SMEM_A_BYTES ((8*2048 + 512 + 2048 + 8) * 4)

extern "C" void kernel_launch(void* const* d_in, const int* in_sizes, int n_in,
                              void* d_out, int out_size) {
    const float* x      = (const float*)d_in[0];
    const float* emb_w  = (const float*)d_in[1];
    const float* emb_b  = (const float*)d_in[2];
    const float* Wq     = (const float*)d_in[3];
    const float* bq     = (const float*)d_in[4];
    const float* Wk     = (const float*)d_in[5];
    const float* bk     = (const float*)d_in[6];
    const float* Wv     = (const float*)d_in[7];
    const float* bv     = (const float*)d_in[8];
    const float* Wo     = (const float*)d_in[9];
    const float* bo     = (const float*)d_in[10];
    const float* W1     = (const float*)d_in[11];
    const float* b1     = (const float*)d_in[12];
    const float* W2     = (const float*)d_in[13];
    const float* b2     = (const float*)d_in[14];
    const float* ln1_g  = (const float*)d_in[15];
    const float* ln1_b  = (const float*)d_in[16];
    const float* ln2_g  = (const float*)d_in[17];
    const float* ln2_b  = (const float*)d_in[18];
    const float* proj_w = (const float*)d_in[19];
    const float* proj_b = (const float*)d_in[20];

    static float *p_h = nullptr, *p_q, *p_k, *p_v, *p_t1, *p_t2, *p_M,
                 *p_ksum, *p_vmean, *p_upd, *p_base;
    static int *p_idx;
    if (!p_h) {
        cudaGetSymbolAddress((void**)&p_h,    g_h);
        cudaGetSymbolAddress((void**)&p_q,    g_q);
        cudaGetSymbolAddress((void**)&p_k,    g_k);
        cudaGetSymbolAddress((void**)&p_v,    g_v);
        cudaGetSymbolAddress((void**)&p_t1,   g_t1);
        cudaGetSymbolAddress((void**)&p_t2,   g_t2);
        cudaGetSymbolAddress((void**)&p_M,    g_M);
        cudaGetSymbolAddress((void**)&p_idx,  g_idx);
        cudaGetSymbolAddress((void**)&p_ksum, g_ksum);
        cudaGetSymbolAddress((void**)&p_vmean,g_vmean);
        cudaGetSymbolAddress((void**)&p_upd,  g_upd);
        cudaGetSymbolAddress((void**)&p_base, g_base);
        cudaFuncSetAttribute(m_kernel,    cudaFuncAttributeMaxDynamicSharedMemorySize, SMEM_M_BYTES);
        cudaFuncSetAttribute(attn_kernel, cudaFuncAttributeMaxDynamicSharedMemorySize, SMEM_A_BYTES);
    }

    embed_kernel<<<(BB*LL*DD)/256, 256>>>(x, emb_w, emb_b, p_h);

    dim3 gg(MROWS/128, DD/128);
    for (int il = 0; il < NL; ++il) {
        const size_t wo = (size_t)il * DD * DD;
        const size_t boff = (size_t)il * DD;
        gemm_dd<2><<<gg, 256>>>(p_h, Wq + wo, bq + boff, p_q);
        gemm_dd<2><<<gg, 256>>>(p_h, Wk + wo, bk + boff, p_k);
        gemm_dd<2><<<gg, 256>>>(p_h, Wv + wo, bv + boff, p_v);
        sums_kernel<<<BH, 256>>>(p_k, p_v, p_ksum, p_vmean);
        m_kernel<<<dim3(LL/128, BH), 256, SMEM_M_BYTES>>>(p_q, p_k, p_ksum, p_M);
        topk_kernel<<<BH, 256>>>(p_M, p_idx);
        attn_kernel<<<dim3(BH, UU/8), 256, SMEM_A_BYTES>>>(p_q, p_k, p_v, p_idx, p_upd);
        base_kernel<<<BB, 512>>>(p_vmean, Wo + wo, bo + boff, p_base);
        cudaMemsetAsync(p_t2, 0, (size_t)BB*LL*DD*sizeof(float));
        corr_kernel<<<BH*UU, 256>>>(p_upd, p_vmean, Wo + wo, p_idx, p_t2);
        addln_base_kernel<<<MROWS, 256>>>(p_h, p_t2, p_base, ln1_g + boff, ln1_b + boff);
        gemm_dd<1><<<gg, 256>>>(p_h, W1 + wo, b1 + boff, p_t1);
        gemm_dd<0><<<gg, 256>>>(p_t1, W2 + wo, b2 + boff, p_t2);
        addln_kernel<<<MROWS, 256>>>(p_h, p_t2, ln2_g + boff, ln2_b + boff);
    }

    proj_kernel<<<BB*PP, 64>>>(p_h, proj_w, proj_b, (float*)d_out);
}

// round 9
// speedup vs baseline: 1.2697x; 1.0000x over previous
#include <cuda_runtime.h>
#include <math.h>

#define BB   4
#define LL   2048
#define EE   7
#define DD   512
#define HH   8
#define DH   64
#define PP   720
#define NL   2
#define UU   40
#define BH   (BB*HH)          // 32
#define MROWS (BB*LL)         // 8192
#define SCALE 0.125f

typedef unsigned long long ull;

__device__ __forceinline__ void ffma2(ull &d, ull a, ull b) {
    asm("fma.rn.f32x2 %0, %1, %2, %0;" : "+l"(d) : "l"(a), "l"(b));
}
__device__ __forceinline__ ull pack2(float x, float y) {
    ull r; asm("mov.b64 %0, {%1, %2};" : "=l"(r) : "f"(x), "f"(y)); return r;
}
__device__ __forceinline__ float2 unpack2(ull p) {
    float2 r; asm("mov.b64 {%0, %1}, %2;" : "=f"(r.x), "=f"(r.y) : "l"(p)); return r;
}

// ---------------- scratch ---------------------------------------------------
__device__ float g_h [BB*LL*DD];
__device__ float g_q [BH*LL*DH];
__device__ float g_k [BH*LL*DH];
__device__ float g_v [BH*LL*DH];
__device__ float g_t1[BB*LL*DD];
__device__ float g_t2[BB*LL*DD];
__device__ float g_M [BH*LL];
__device__ int   g_idx[BH*UU];
__device__ float g_ksum [BH*DH];
__device__ float g_vmean[BH*DH];
__device__ float g_upd[BH*UU*DH];
__device__ float g_base[BB*DD];

// ---------------- embedding -------------------------------------------------
__global__ void embed_kernel(const float* __restrict__ x,
                             const float* __restrict__ w,
                             const float* __restrict__ b,
                             float* __restrict__ out) {
    int i = blockIdx.x * 256 + threadIdx.x;
    int row = i >> 9;
    int n   = i & 511;
    float acc = b[n];
    #pragma unroll
    for (int e = 0; e < EE; ++e)
        acc += x[row*EE + e] * w[e*DD + n];
    out[i] = acc;
}

// ---------------- GEMM [8192,512]x[512,512]+bias, f32x2 ---------------------
// MODE 0: plain; 1: relu; 2: scatter to head layout [B,H,L,DH]
template<int MODE>
__global__ __launch_bounds__(256, 2)
void gemm_dd(const float* __restrict__ A, const float* __restrict__ W,
             const float* __restrict__ bias, float* __restrict__ out) {
    __shared__ float As[128][32];
    __shared__ float Bs[32][132];
    const int tid = threadIdx.x;
    const int tx = tid & 15, ty = tid >> 4;
    const int m0 = blockIdx.x * 128, n0 = blockIdx.y * 128;
    ull acc[8][4];
    #pragma unroll
    for (int i = 0; i < 8; ++i)
        #pragma unroll
        for (int j = 0; j < 4; ++j) acc[i][j] = 0ull;

    for (int k0 = 0; k0 < 512; k0 += 32) {
        __syncthreads();
        #pragma unroll
        for (int t = 0; t < 4; ++t) {                // A: 128x32
            int i = tid + t * 256;
            int r = i >> 3, c = (i & 7) * 4;
            *(float4*)&As[r][c] = *(const float4*)&A[(size_t)(m0 + r)*512 + k0 + c];
        }
        #pragma unroll
        for (int t = 0; t < 4; ++t) {                // B: 32x128
            int i = tid + t * 256;
            int r = i >> 5, c = (i & 31) * 4;
            *(float4*)&Bs[r][c] = *(const float4*)&W[(size_t)(k0 + r)*512 + n0 + c];
        }
        __syncthreads();
        #pragma unroll 4
        for (int kk = 0; kk < 32; ++kk) {
            ull bfr[4];
            #pragma unroll
            for (int j = 0; j < 4; ++j)
                bfr[j] = *(const ull*)&Bs[kk][j*32 + tx*2];
            #pragma unroll
            for (int i = 0; i < 8; ++i) {
                float av = As[ty*8 + i][kk];
                ull aa = pack2(av, av);
                #pragma unroll
                for (int j = 0; j < 4; ++j) ffma2(acc[i][j], aa, bfr[j]);
            }
        }
    }
    #pragma unroll
    for (int i = 0; i < 8; ++i) {
        int m = m0 + ty*8 + i;
        int b_ = m >> 11, l_ = m & 2047;
        #pragma unroll
        for (int j = 0; j < 4; ++j) {
            int n = n0 + j*32 + tx*2;
            float2 v = unpack2(acc[i][j]);
            float2 b2 = *(const float2*)&bias[n];
            v.x += b2.x; v.y += b2.y;
            if (MODE == 1) { v.x = fmaxf(v.x, 0.f); v.y = fmaxf(v.y, 0.f); }
            if (MODE == 2) {
                int hh = n >> 6, dh = n & 63;
                *(float2*)&out[(((size_t)(b_*HH + hh))*LL + l_)*DH + dh] = v;
            } else {
                *(float2*)&out[(size_t)m*512 + n] = v;
            }
        }
    }
}

// ---------------- per-(b,h) sums --------------------------------------------
__global__ void sums_kernel(const float* __restrict__ k,
                            const float* __restrict__ v,
                            float* __restrict__ ksum,
                            float* __restrict__ vmean) {
    int bh = blockIdx.x, tid = threadIdx.x;   // 256
    int d = tid & 63, c = tid >> 6;
    const float* kb = k + (size_t)bh * LL * DH + d;
    const float* vb = v + (size_t)bh * LL * DH + d;
    float ks = 0.f, vs = 0.f;
    for (int l = c; l < LL; l += 4) { ks += kb[(size_t)l*DH]; vs += vb[(size_t)l*DH]; }
    __shared__ float rk[4][64], rv[4][64];
    rk[c][d] = ks; rv[c][d] = vs;
    __syncthreads();
    if (tid < 64) {
        float a = rk[0][tid] + rk[1][tid] + rk[2][tid] + rk[3][tid];
        float m = rv[0][tid] + rv[1][tid] + rv[2][tid] + rv[3][tid];
        ksum [bh*DH + tid] = a;
        vmean[bh*DH + tid] = m * (1.f / LL);
    }
}

// ---------------- M(q) via 128x128 f32x2 score tiles ------------------------
__global__ __launch_bounds__(256, 2)
void m_kernel(const float* __restrict__ q, const float* __restrict__ k,
              const float* __restrict__ ksum, float* __restrict__ Mout) {
    extern __shared__ float sm[];
    float (*Qs)[64]  = (float(*)[64])sm;                 // 128x64
    float (*Ks)[132] = (float(*)[132])(sm + 128*64);     // 64x132
    float* red = sm + 128*64 + 64*132;                   // 128
    int bh = blockIdx.y, q0 = blockIdx.x * 128;
    const float* qb = q + (size_t)bh * LL * DH;
    const float* kb = k + (size_t)bh * LL * DH;
    int tid = threadIdx.x;
    int tx = tid & 15, ty = tid >> 4;

    #pragma unroll
    for (int t = 0; t < 8; ++t) {                        // Q: coalesced, row-major
        int i = tid + t * 256;
        int r = i >> 4, c = (i & 15) * 4;
        *(float4*)&Qs[r][c] = *(const float4*)&qb[(size_t)(q0 + r)*DH + c];
    }
    float rmax[8];
    #pragma unroll
    for (int i = 0; i < 8; ++i) rmax[i] = -INFINITY;

    for (int kt = 0; kt < LL/128; ++kt) {
        __syncthreads();
        #pragma unroll
        for (int t = 0; t < 8; ++t) {                    // K: transposed into smem
            int i = tid + t * 256;
            int r = i & 127, c = (i >> 7) * 4;
            float4 kv = *(const float4*)&kb[(size_t)(kt*128 + r)*DH + c];
            Ks[c+0][r] = kv.x; Ks[c+1][r] = kv.y; Ks[c+2][r] = kv.z; Ks[c+3][r] = kv.w;
        }
        __syncthreads();
        ull acc[8][4];
        #pragma unroll
        for (int i = 0; i < 8; ++i)
            #pragma unroll
            for (int j = 0; j < 4; ++j) acc[i][j] = 0ull;
        #pragma unroll 4
        for (int d = 0; d < 64; ++d) {
            ull bfr[4];
            #pragma unroll
            for (int j = 0; j < 4; ++j)
                bfr[j] = *(const ull*)&Ks[d][j*32 + tx*2];
            #pragma unroll
            for (int i = 0; i < 8; ++i) {
                float av = Qs[ty*8 + i][d];
                ull aa = pack2(av, av);
                #pragma unroll
                for (int j = 0; j < 4; ++j) ffma2(acc[i][j], aa, bfr[j]);
            }
        }
        #pragma unroll
        for (int i = 0; i < 8; ++i)
            #pragma unroll
            for (int j = 0; j < 4; ++j) {
                float2 v = unpack2(acc[i][j]);
                rmax[i] = fmaxf(rmax[i], fmaxf(v.x, v.y));
            }
    }
    #pragma unroll
    for (int i = 0; i < 8; ++i) {
        #pragma unroll
        for (int o = 1; o < 16; o <<= 1)
            rmax[i] = fmaxf(rmax[i], __shfl_xor_sync(0xffffffffu, rmax[i], o));
    }
    if (tx == 0) {
        #pragma unroll
        for (int i = 0; i < 8; ++i) red[ty*8 + i] = rmax[i];
    }
    __syncthreads();
    if (tid < 128) {
        const float* ks = ksum + bh * DH;
        float dot = 0.f;
        #pragma unroll
        for (int dd = 0; dd < 64; ++dd) {
            int d = (dd + tid) & 63;                     // rotate: conflict-free smem
            dot += Qs[tid][d] * ks[d];
        }
        Mout[bh*LL + q0 + tid] = (red[tid] - dot * (1.f / LL)) * SCALE;
    }
}

// ---------------- top-U selection per (b,h) ---------------------------------
__global__ void topk_kernel(const float* __restrict__ M, int* __restrict__ idxout) {
    int bh = blockIdx.x, tid = threadIdx.x;
    __shared__ float sm[LL];
    __shared__ float bv[256];
    __shared__ int   bi[256];
    for (int l = tid; l < LL; l += 256) sm[l] = M[bh*LL + l];
    __syncthreads();
    for (int it = 0; it < UU; ++it) {
        float best = -INFINITY; int bidx = LL;
        for (int l = tid; l < LL; l += 256) {
            float v = sm[l];
            if (v > best || (v == best && l < bidx)) { best = v; bidx = l; }
        }
        bv[tid] = best; bi[tid] = bidx;
        __syncthreads();
        for (int s = 128; s > 0; s >>= 1) {
            if (tid < s) {
                if (bv[tid+s] > bv[tid] || (bv[tid+s] == bv[tid] && bi[tid+s] < bi[tid])) {
                    bv[tid] = bv[tid+s]; bi[tid] = bi[tid+s];
                }
            }
            __syncthreads();
        }
        if (tid == 0) { idxout[bh*UU + it] = bi[0]; sm[bi[0]] = -INFINITY; }
        __syncthreads();
    }
}

// ---------------- attention: 8 active queries per block ---------------------
__global__ __launch_bounds__(256, 2)
void attn_kernel(const float* __restrict__ q, const float* __restrict__ k,
                 const float* __restrict__ v, const int* __restrict__ idx,
                 float* __restrict__ upd) {
    extern __shared__ float sb[];
    float* sc   = sb;                  // 8*2048
    float* qv   = sb + 8*2048;         // 8*64
    float* red  = qv + 512;            // 4*8*64
    float* sinv = red + 2048;          // 8
    int bh = blockIdx.x, u0 = blockIdx.y * 8;
    int tid = threadIdx.x;
    const float* kb = k + (size_t)bh * LL * DH;
    const float* vb = v + (size_t)bh * LL * DH;

    for (int i = tid; i < 8*64; i += 256) {
        int u = i >> 6, d = i & 63;
        int lq = idx[bh*UU + u0 + u];
        qv[i] = q[((size_t)bh*LL + lq)*DH + d];
    }
    __syncthreads();

    for (int l = tid; l < LL; l += 256) {
        const float4* kr = (const float4*)(kb + (size_t)l*DH);
        float acc[8];
        #pragma unroll
        for (int u = 0; u < 8; ++u) acc[u] = 0.f;
        #pragma unroll
        for (int t = 0; t < 16; ++t) {
            float4 kv = kr[t];
            #pragma unroll
            for (int u = 0; u < 8; ++u) {
                float4 qq = *(const float4*)&qv[u*64 + t*4];
                acc[u] += kv.x*qq.x + kv.y*qq.y + kv.z*qq.z + kv.w*qq.w;
            }
        }
        #pragma unroll
        for (int u = 0; u < 8; ++u) sc[u*2048 + l] = acc[u] * SCALE;
    }
    __syncthreads();

    {   // per-warp softmax (warp u handles query u)
        int u = tid >> 5, lane = tid & 31;
        float m = -INFINITY;
        for (int l = lane; l < LL; l += 32) m = fmaxf(m, sc[u*2048 + l]);
        #pragma unroll
        for (int o = 16; o > 0; o >>= 1) m = fmaxf(m, __shfl_xor_sync(0xffffffffu, m, o));
        float s = 0.f;
        for (int l = lane; l < LL; l += 32) {
            float e = __expf(sc[u*2048 + l] - m);
            sc[u*2048 + l] = e; s += e;
        }
        #pragma unroll
        for (int o = 16; o > 0; o >>= 1) s += __shfl_xor_sync(0xffffffffu, s, o);
        if (lane == 0) sinv[u] = 1.f / s;
    }
    __syncthreads();

    int d = tid & 63, lc = tid >> 6;
    float acc[8];
    #pragma unroll
    for (int u = 0; u < 8; ++u) acc[u] = 0.f;
    for (int l = lc; l < LL; l += 4) {
        float vv = vb[(size_t)l*DH + d];
        #pragma unroll
        for (int u = 0; u < 8; ++u) acc[u] += sc[u*2048 + l] * vv;
    }
    #pragma unroll
    for (int u = 0; u < 8; ++u) red[(lc*8 + u)*64 + d] = acc[u];
    __syncthreads();
    if (tid < 64) {
        #pragma unroll
        for (int u = 0; u < 8; ++u) {
            float t = red[u*64 + tid] + red[(8+u)*64 + tid] +
                      red[(16+u)*64 + tid] + red[(24+u)*64 + tid];
            upd[((size_t)bh*UU + u0 + u)*DH + tid] = t * sinv[u];
        }
    }
}

// ---------------- base = vmeanCat @ Wo + bo  (4 rows) -----------------------
__global__ void base_kernel(const float* __restrict__ vmean,
                            const float* __restrict__ Wo,
                            const float* __restrict__ bo,
                            float* __restrict__ base) {
    int b = blockIdx.x, n = threadIdx.x;        // 512 threads
    const float* vm = vmean + b * 512;          // [h*64+d] ordering == D cols
    float acc = bo[n];
    for (int kk = 0; kk < 512; ++kk)
        acc += vm[kk] * Wo[(size_t)kk*512 + n];
    base[b*512 + n] = acc;
}

// ---------------- sparse corrections: (upd - vmean_h) @ Wo_h ----------------
__global__ void corr_kernel(const float* __restrict__ upd,
                            const float* __restrict__ vmean,
                            const float* __restrict__ Wo,
                            const int* __restrict__ idx,
                            float* __restrict__ delta) {
    int blk = blockIdx.x;                       // bh*UU + u
    int bh = blk / UU, u = blk % UU;
    int h = bh & 7, b = bh >> 3;
    __shared__ float du[64];
    int tid = threadIdx.x;                      // 256
    if (tid < 64) du[tid] = upd[(size_t)blk*64 + tid] - vmean[bh*64 + tid];
    __syncthreads();
    int l = idx[bh*UU + u];
    float* drow = delta + ((size_t)b*LL + l)*DD;
    const float* wrow = Wo + (size_t)h*64*512;
    #pragma unroll
    for (int half = 0; half < 2; ++half) {
        int n = tid + half*256;
        float acc = 0.f;
        #pragma unroll 8
        for (int d = 0; d < 64; ++d) acc += du[d] * wrow[(size_t)d*512 + n];
        atomicAdd(&drow[n], acc);
    }
}

// ---------------- residual + LayerNorm variants -----------------------------
__global__ void addln_base_kernel(float* h, const float* __restrict__ delta,
                                  const float* __restrict__ base,
                                  const float* __restrict__ g, const float* __restrict__ b) {
    int row = blockIdx.x, tid = threadIdx.x;    // 256
    int bb_ = row >> 11;
    float* hr = h + (size_t)row * DD;
    const float* dr = delta + (size_t)row * DD;
    const float* br = base + bb_ * DD;
    __shared__ float rbuf[8];
    __shared__ float sh_mean, sh_var;
    float s0 = hr[tid]       + dr[tid]       + br[tid];
    float s1 = hr[tid + 256] + dr[tid + 256] + br[tid + 256];
    float s = s0 + s1;
    for (int o = 16; o > 0; o >>= 1) s += __shfl_down_sync(0xffffffffu, s, o);
    if ((tid & 31) == 0) rbuf[tid >> 5] = s;
    __syncthreads();
    if (tid == 0) {
        float t = 0.f;
        #pragma unroll
        for (int i = 0; i < 8; ++i) t += rbuf[i];
        sh_mean = t * (1.f / DD);
    }
    __syncthreads();
    float mval = sh_mean;
    float d0 = s0 - mval, d1 = s1 - mval;
    float vv = d0*d0 + d1*d1;
    for (int o = 16; o > 0; o >>= 1) vv += __shfl_down_sync(0xffffffffu, vv, o);
    if ((tid & 31) == 0) rbuf[tid >> 5] = vv;
    __syncthreads();
    if (tid == 0) {
        float t = 0.f;
        #pragma unroll
        for (int i = 0; i < 8; ++i) t += rbuf[i];
        sh_var = t * (1.f / DD);
    }
    __syncthreads();
    float inv = rsqrtf(sh_var + 1e-5f);
    hr[tid]       = d0 * inv * g[tid]       + b[tid];
    hr[tid + 256] = d1 * inv * g[tid + 256] + b[tid + 256];
}

__global__ void addln_kernel(float* h, const float* __restrict__ a,
                             const float* __restrict__ g, const float* __restrict__ b) {
    int row = blockIdx.x, tid = threadIdx.x;
    float* hr = h + (size_t)row * DD;
    const float* ar = a + (size_t)row * DD;
    __shared__ float rbuf[8];
    __shared__ float sh_mean, sh_var;
    float s0 = hr[tid]       + ar[tid];
    float s1 = hr[tid + 256] + ar[tid + 256];
    float s = s0 + s1;
    for (int o = 16; o > 0; o >>= 1) s += __shfl_down_sync(0xffffffffu, s, o);
    if ((tid & 31) == 0) rbuf[tid >> 5] = s;
    __syncthreads();
    if (tid == 0) {
        float t = 0.f;
        #pragma unroll
        for (int i = 0; i < 8; ++i) t += rbuf[i];
        sh_mean = t * (1.f / DD);
    }
    __syncthreads();
    float mval = sh_mean;
    float d0 = s0 - mval, d1 = s1 - mval;
    float vv = d0*d0 + d1*d1;
    for (int o = 16; o > 0; o >>= 1) vv += __shfl_down_sync(0xffffffffu, vv, o);
    if ((tid & 31) == 0) rbuf[tid >> 5] = vv;
    __syncthreads();
    if (tid == 0) {
        float t = 0.f;
        #pragma unroll
        for (int i = 0; i < 8; ++i) t += rbuf[i];
        sh_var = t * (1.f / DD);
    }
    __syncthreads();
    float inv = rsqrtf(sh_var + 1e-5f);
    hr[tid]       = d0 * inv * g[tid]       + b[tid];
    hr[tid + 256] = d1 * inv * g[tid + 256] + b[tid + 256];
}

// ---------------- final projection ------------------------------------------
__global__ void proj_kernel(const float* __restrict__ h,
                            const float* __restrict__ pw,
                            const float* __restrict__ pb,
                            float* __restrict__ out) {
    int bp = blockIdx.x;
    int b = bp / PP, p = bp % PP;
    int l = LL - PP + p;
    int tid = threadIdx.x;                     // 64
    const float* hr = h + ((size_t)b*LL + l)*DD;
    float acc[EE];
    #pragma unroll
    for (int e = 0; e < EE; ++e) acc[e] = 0.f;
    for (int kk = tid; kk < DD; kk += 64) {
        float hv = hr[kk];
        #pragma unroll
        for (int e = 0; e < EE; ++e) acc[e] += hv * pw[kk*EE + e];
    }
    __shared__ float red[EE][64];
    #pragma unroll
    for (int e = 0; e < EE; ++e) red[e][tid] = acc[e];
    __syncthreads();
    if (tid < EE) {
        float t = 0.f;
        for (int i = 0; i < 64; ++i) t += red[tid][i];
        out[(size_t)bp * EE + tid] = t + pb[tid];
    }
}

// ---------------- host driver ------------------------------------------------
#define SMEM_M_BYTES ((128*64 + 64*132 + 128) * 4)
#define SMEM_A_BYTES ((8*2048 + 512 + 2048 + 8) * 4)

extern "C" void kernel_launch(void* const* d_in, const int* in_sizes, int n_in,
                              void* d_out, int out_size) {
    const float* x      = (const float*)d_in[0];
    const float* emb_w  = (const float*)d_in[1];
    const float* emb_b  = (const float*)d_in[2];
    const float* Wq     = (const float*)d_in[3];
    const float* bq     = (const float*)d_in[4];
    const float* Wk     = (const float*)d_in[5];
    const float* bk     = (const float*)d_in[6];
    const float* Wv     = (const float*)d_in[7];
    const float* bv     = (const float*)d_in[8];
    const float* Wo     = (const float*)d_in[9];
    const float* bo     = (const float*)d_in[10];
    const float* W1     = (const float*)d_in[11];
    const float* b1     = (const float*)d_in[12];
    const float* W2     = (const float*)d_in[13];
    const float* b2     = (const float*)d_in[14];
    const float* ln1_g  = (const float*)d_in[15];
    const float* ln1_b  = (const float*)d_in[16];
    const float* ln2_g  = (const float*)d_in[17];
    const float* ln2_b  = (const float*)d_in[18];
    const float* proj_w = (const float*)d_in[19];
    const float* proj_b = (const float*)d_in[20];

    static float *p_h = nullptr, *p_q, *p_k, *p_v, *p_t1, *p_t2, *p_M,
                 *p_ksum, *p_vmean, *p_upd, *p_base;
    static int *p_idx;
    if (!p_h) {
        cudaGetSymbolAddress((void**)&p_h,    g_h);
        cudaGetSymbolAddress((void**)&p_q,    g_q);
        cudaGetSymbolAddress((void**)&p_k,    g_k);
        cudaGetSymbolAddress((void**)&p_v,    g_v);
        cudaGetSymbolAddress((void**)&p_t1,   g_t1);
        cudaGetSymbolAddress((void**)&p_t2,   g_t2);
        cudaGetSymbolAddress((void**)&p_M,    g_M);
        cudaGetSymbolAddress((void**)&p_idx,  g_idx);
        cudaGetSymbolAddress((void**)&p_ksum, g_ksum);
        cudaGetSymbolAddress((void**)&p_vmean,g_vmean);
        cudaGetSymbolAddress((void**)&p_upd,  g_upd);
        cudaGetSymbolAddress((void**)&p_base, g_base);
        cudaFuncSetAttribute(m_kernel,    cudaFuncAttributeMaxDynamicSharedMemorySize, SMEM_M_BYTES);
        cudaFuncSetAttribute(attn_kernel, cudaFuncAttributeMaxDynamicSharedMemorySize, SMEM_A_BYTES);
    }

    embed_kernel<<<(BB*LL*DD)/256, 256>>>(x, emb_w, emb_b, p_h);

    dim3 gg(MROWS/128, DD/128);
    for (int il = 0; il < NL; ++il) {
        const size_t wo = (size_t)il * DD * DD;
        const size_t boff = (size_t)il * DD;
        gemm_dd<2><<<gg, 256>>>(p_h, Wq + wo, bq + boff, p_q);
        gemm_dd<2><<<gg, 256>>>(p_h, Wk + wo, bk + boff, p_k);
        gemm_dd<2><<<gg, 256>>>(p_h, Wv + wo, bv + boff, p_v);
        sums_kernel<<<BH, 256>>>(p_k, p_v, p_ksum, p_vmean);
        m_kernel<<<dim3(LL/128, BH), 256, SMEM_M_BYTES>>>(p_q, p_k, p_ksum, p_M);
        topk_kernel<<<BH, 256>>>(p_M, p_idx);
        attn_kernel<<<dim3(BH, UU/8), 256, SMEM_A_BYTES>>>(p_q, p_k, p_v, p_idx, p_upd);
        base_kernel<<<BB, 512>>>(p_vmean, Wo + wo, bo + boff, p_base);
        cudaMemsetAsync(p_t2, 0, (size_t)BB*LL*DD*sizeof(float));
        corr_kernel<<<BH*UU, 256>>>(p_upd, p_vmean, Wo + wo, p_idx, p_t2);
        addln_base_kernel<<<MROWS, 256>>>(p_h, p_t2, p_base, ln1_g + boff, ln1_b + boff);
        gemm_dd<1><<<gg, 256>>>(p_h, W1 + wo, b1 + boff, p_t1);
        gemm_dd<0><<<gg, 256>>>(p_t1, W2 + wo, b2 + boff, p_t2);
        addln_kernel<<<MROWS, 256>>>(p_h, p_t2, ln2_g + boff, ln2_b + boff);
    }

    proj_kernel<<<BB*PP, 64>>>(p_h, proj_w, proj_b, (float*)d_out);
}

// round 12
// speedup vs baseline: 1.9516x; 1.5370x over previous
#include <cuda_runtime.h>
#include <cuda_bf16.h>
#include <math.h>
#include <stdint.h>

#define BB   4
#define LL   2048
#define EE   7
#define DD   512
#define HH   8
#define DH   64
#define PP   720
#define NL   2
#define UU   40
#define BH   (BB*HH)
#define MROWS (BB*LL)
#define SCALE 0.125f

typedef unsigned long long ull;
typedef uint32_t u32;
typedef __nv_bfloat16 bf16;

// ===================== warp-MMA helpers (sm_80 baseline PTX) ================
__device__ __forceinline__ u32 smem_u32(const void* p) {
    u32 a;
    asm("{ .reg .u64 t; cvta.to.shared.u64 t, %1; cvt.u32.u64 %0, t; }"
        : "=r"(a) : "l"(p));
    return a;
}
__device__ __forceinline__ void cpasync16(u32 dst, const void* src) {
    asm volatile("cp.async.cg.shared.global [%0], [%1], 16;" :: "r"(dst), "l"(src));
}
#define CP_COMMIT() asm volatile("cp.async.commit_group;" ::: "memory")
#define CP_WAIT(n)  asm volatile("cp.async.wait_group %0;" :: "n"(n) : "memory")

#define LDM4(f, addr) \
    asm volatile("ldmatrix.sync.aligned.m8n8.x4.shared.b16 {%0,%1,%2,%3}, [%4];" \
        : "=r"((f)[0]), "=r"((f)[1]), "=r"((f)[2]), "=r"((f)[3]) : "r"(addr))

#define MMA(c, a, b0, b1) \
    asm volatile("mma.sync.aligned.m16n8k16.row.col.f32.bf16.bf16.f32 " \
        "{%0,%1,%2,%3}, {%4,%5,%6,%7}, {%8,%9}, {%0,%1,%2,%3};" \
        : "+f"((c)[0]), "+f"((c)[1]), "+f"((c)[2]), "+f"((c)[3]) \
        : "r"((a)[0]), "r"((a)[1]), "r"((a)[2]), "r"((a)[3]), "r"(b0), "r"(b1))

// ===================== scratch =============================================
__device__ float g_h [BB*LL*DD];
__device__ float g_q [BH*LL*DH];
__device__ float g_k [BH*LL*DH];
__device__ float g_v [BH*LL*DH];
__device__ float g_t1[BB*LL*DD];
__device__ float g_t2[BB*LL*DD];
__device__ float g_M [BH*LL];
__device__ int   g_idx[BH*UU];
__device__ float g_ksum [BH*DH];
__device__ float g_vmean[BH*DH];
__device__ float g_upd[BH*UU*DH];
__device__ float g_base[BB*DD];
__device__ bf16 g_ah[MROWS*DD];
__device__ bf16 g_al[MROWS*DD];
__device__ bf16 g_wh[5*DD*DD];
__device__ bf16 g_wl[5*DD*DD];
__device__ bf16 g_qh[BH*LL*DH];
__device__ bf16 g_ql[BH*LL*DH];
__device__ bf16 g_kh[BH*LL*DH];
__device__ bf16 g_kl[BH*LL*DH];

// ===================== conversions =========================================
__global__ void split_kernel(const float* __restrict__ in,
                             bf16* __restrict__ hi, bf16* __restrict__ lo) {
    int i = blockIdx.x * 256 + threadIdx.x;       // over N/4
    float4 f = ((const float4*)in)[i];
    __nv_bfloat162 h0 = __floats2bfloat162_rn(f.x, f.y);
    __nv_bfloat162 h1 = __floats2bfloat162_rn(f.z, f.w);
    float2 h0f = __bfloat1622float2(h0), h1f = __bfloat1622float2(h1);
    __nv_bfloat162 l0 = __floats2bfloat162_rn(f.x - h0f.x, f.y - h0f.y);
    __nv_bfloat162 l1 = __floats2bfloat162_rn(f.z - h1f.x, f.w - h1f.y);
    ((uint2*)hi)[i] = make_uint2(*(u32*)&h0, *(u32*)&h1);
    ((uint2*)lo)[i] = make_uint2(*(u32*)&l0, *(u32*)&l1);
}

// W [k][n] fp32 -> Wt [n][k] bf16 hi/lo; 5 weight slots via blockIdx.z
__global__ void wsplit_kernel(const float* __restrict__ Wq, const float* __restrict__ Wk,
                              const float* __restrict__ Wv, const float* __restrict__ W1,
                              const float* __restrict__ W2,
                              bf16* __restrict__ wh, bf16* __restrict__ wl) {
    int slot = blockIdx.z;
    const float* W = (slot == 0) ? Wq : (slot == 1) ? Wk : (slot == 2) ? Wv
                   : (slot == 3) ? W1 : W2;
    __shared__ float ts[32][33];
    int n0 = blockIdx.x * 32, k0 = blockIdx.y * 32;
    int tx = threadIdx.x, ty = threadIdx.y;      // (32, 8)
    #pragma unroll
    for (int i = 0; i < 4; ++i)
        ts[ty + i*8][tx] = W[(size_t)(k0 + ty + i*8) * 512 + n0 + tx];
    __syncthreads();
    size_t so = (size_t)slot * DD * DD;
    #pragma unroll
    for (int i = 0; i < 4; ++i) {
        float v = ts[tx][ty + i*8];
        bf16 h = __float2bfloat16(v);
        bf16 l = __float2bfloat16(v - __bfloat162float(h));
        size_t o = so + (size_t)(n0 + ty + i*8) * 512 + k0 + tx;
        wh[o] = h; wl[o] = l;
    }
}

// ===================== embedding ===========================================
__global__ void embed_kernel(const float* __restrict__ x,
                             const float* __restrict__ w,
                             const float* __restrict__ b,
                             float* __restrict__ out) {
    int i = blockIdx.x * 256 + threadIdx.x;
    int row = i >> 9, n = i & 511;
    float acc = b[n];
    #pragma unroll
    for (int e = 0; e < EE; ++e) acc += x[row*EE + e] * w[e*DD + n];
    out[i] = acc;
}

// ===================== warp-MMA GEMM [8192,512]x[512,512] ===================
// A row-major hi/lo; W pre-transposed [n][k] hi/lo. 3-term split.
// MODE 0: plain; 1: relu; 2: head-layout scatter
#define GK 32                  // K per chunk (bf16)
#define GPAD 40                // padded row length (elements)
#define GARR (2*128*GPAD)      // one hi-or-lo array, 2 buffers, elements
template<int MODE>
__global__ __launch_bounds__(256, 1)
void gemm_mma(const bf16* __restrict__ ah, const bf16* __restrict__ al,
              const bf16* __restrict__ wh, const bf16* __restrict__ wl,
              const float* __restrict__ bias, float* __restrict__ out) {
    extern __shared__ bf16 sm[];
    bf16* pAh = sm;
    bf16* pAl = pAh + GARR;
    bf16* pBh = pAl + GARR;
    bf16* pBl = pBh + GARR;
    const int tid = threadIdx.x, lane = tid & 31, wid = tid >> 5;
    const int wm = wid & 3, wn = wid >> 2;            // warp 32x64 tile
    const int m0 = blockIdx.x * 128, n0 = blockIdx.y * 128;

    const u32 sAh = smem_u32(pAh), sAl = smem_u32(pAl);
    const u32 sBh = smem_u32(pBh), sBl = smem_u32(pBl);

    float acc[2][8][4];
    #pragma unroll
    for (int a = 0; a < 2; ++a)
        #pragma unroll
        for (int n = 0; n < 8; ++n)
            #pragma unroll
            for (int j = 0; j < 4; ++j) acc[a][n][j] = 0.f;

    // chunk loader: 512 u4 per array -> 2 per thread per array
    auto load_chunk = [&](int c, int buf) {
        int kb = c * GK;
        #pragma unroll
        for (int u = 0; u < 2; ++u) {
            int i = tid + u * 256;
            int r = i >> 2, j = (i & 3) * 8;
            u32 doff = (u32)((buf * 128 * GPAD + r * GPAD + j) * 2);
            cpasync16(sAh + doff, ah + (size_t)(m0 + r) * 512 + kb + j);
            cpasync16(sAl + doff, al + (size_t)(m0 + r) * 512 + kb + j);
            cpasync16(sBh + doff, wh + (size_t)(n0 + r) * 512 + kb + j);
            cpasync16(sBl + doff, wl + (size_t)(n0 + r) * 512 + kb + j);
        }
        CP_COMMIT();
    };

    load_chunk(0, 0);
    for (int c = 0; c < 16; ++c) {
        int buf = c & 1;
        if (c < 15) load_chunk(c + 1, buf ^ 1);
        if (c < 15) CP_WAIT(1); else CP_WAIT(0);
        __syncthreads();
        u32 bofs = (u32)(buf * 128 * GPAD * 2);
        #pragma unroll
        for (int s = 0; s < 2; ++s) {
            int colb = (s * 16 + (lane >> 4) * 8) * 2;
            u32 fa[2][4], fal[2][4];
            #pragma unroll
            for (int a = 0; a < 2; ++a) {
                u32 ro = (u32)((wm * 32 + a * 16 + (lane & 15)) * GPAD * 2) + colb + bofs;
                LDM4(fa[a],  sAh + ro);
                LDM4(fal[a], sAl + ro);
            }
            u32 fbh[4][4], fbl[4][4];
            #pragma unroll
            for (int p = 0; p < 4; ++p) {
                u32 ro = (u32)((wn * 64 + p * 16 + (lane & 15)) * GPAD * 2) + colb + bofs;
                LDM4(fbh[p], sBh + ro);
                LDM4(fbl[p], sBl + ro);
            }
            #pragma unroll
            for (int a = 0; a < 2; ++a)
                #pragma unroll
                for (int p = 0; p < 4; ++p) {
                    MMA(acc[a][2*p],   fa[a],  fbh[p][0], fbh[p][2]);
                    MMA(acc[a][2*p+1], fa[a],  fbh[p][1], fbh[p][3]);
                    MMA(acc[a][2*p],   fa[a],  fbl[p][0], fbl[p][2]);
                    MMA(acc[a][2*p+1], fa[a],  fbl[p][1], fbl[p][3]);
                    MMA(acc[a][2*p],   fal[a], fbh[p][0], fbh[p][2]);
                    MMA(acc[a][2*p+1], fal[a], fbh[p][1], fbh[p][3]);
                }
        }
        __syncthreads();
    }

    // epilogue: direct stores (float2 per atom fragment)
    int rg = m0 + wm * 32 + (lane >> 2);
    int cg = n0 + wn * 64 + (lane & 3) * 2;
    #pragma unroll
    for (int a = 0; a < 2; ++a)
        #pragma unroll
        for (int n = 0; n < 8; ++n) {
            int col = cg + n * 8;
            float2 bv = *(const float2*)&bias[col];
            #pragma unroll
            for (int hf = 0; hf < 2; ++hf) {
                int row = rg + a * 16 + hf * 8;
                float2 v = make_float2(acc[a][n][hf*2] + bv.x, acc[a][n][hf*2+1] + bv.y);
                if (MODE == 1) { v.x = fmaxf(v.x, 0.f); v.y = fmaxf(v.y, 0.f); }
                if (MODE == 2) {
                    int hh = col >> 6, dh = col & 63, b_ = row >> 11, l_ = row & 2047;
                    *(float2*)&out[(((size_t)(b_*HH + hh))*LL + l_)*DH + dh] = v;
                } else {
                    *(float2*)&out[(size_t)row * 512 + col] = v;
                }
            }
        }
}

// ===================== M(q) via warp MMA ===================================
// scores tile 128q x 128k, K-dim 64; q/k pre-split bf16 hi/lo in head layout
#define MPAD 72
__global__ __launch_bounds__(256, 1)
void m_mma(const bf16* __restrict__ qh, const bf16* __restrict__ ql,
           const bf16* __restrict__ kh, const bf16* __restrict__ kl,
           const float* __restrict__ ksum, float* __restrict__ Mout) {
    extern __shared__ bf16 sm[];
    bf16* pQh = sm;                        // 128*72
    bf16* pQl = pQh + 128*MPAD;
    bf16* pKh = pQl + 128*MPAD;            // 2 buffers
    bf16* pKl = pKh + 2*128*MPAD;
    float* red = (float*)(pKl + 2*128*MPAD);   // [2][128]
    const int tid = threadIdx.x, lane = tid & 31, wid = tid >> 5;
    const int wm = wid & 3, wn = wid >> 2;
    const int bh = blockIdx.y, q0 = blockIdx.x * 128;
    const bf16* qhb = qh + (size_t)bh * LL * DH;
    const bf16* qlb = ql + (size_t)bh * LL * DH;
    const bf16* khb = kh + (size_t)bh * LL * DH;
    const bf16* klb = kl + (size_t)bh * LL * DH;
    const u32 sQh = smem_u32(pQh), sQl = smem_u32(pQl);
    const u32 sKh = smem_u32(pKh), sKl = smem_u32(pKl);

    // stage Q once: 1024 u4 per array -> 4 per thread
    #pragma unroll
    for (int u = 0; u < 4; ++u) {
        int i = tid + u * 256;
        int r = i >> 3, j = (i & 7) * 8;
        u32 doff = (u32)((r * MPAD + j) * 2);
        cpasync16(sQh + doff, qhb + (size_t)(q0 + r) * 64 + j);
        cpasync16(sQl + doff, qlb + (size_t)(q0 + r) * 64 + j);
    }
    CP_COMMIT();

    auto load_k = [&](int t, int buf) {
        #pragma unroll
        for (int u = 0; u < 4; ++u) {
            int i = tid + u * 256;
            int r = i >> 3, j = (i & 7) * 8;
            u32 doff = (u32)((buf * 128 * MPAD + r * MPAD + j) * 2);
            cpasync16(sKh + doff, khb + (size_t)(t * 128 + r) * 64 + j);
            cpasync16(sKl + doff, klb + (size_t)(t * 128 + r) * 64 + j);
        }
        CP_COMMIT();
    };

    load_k(0, 0);
    float rmax[2][2];
    #pragma unroll
    for (int a = 0; a < 2; ++a) { rmax[a][0] = -INFINITY; rmax[a][1] = -INFINITY; }

    for (int t = 0; t < 16; ++t) {
        int buf = t & 1;
        if (t < 15) load_k(t + 1, buf ^ 1);
        if (t < 15) CP_WAIT(1); else CP_WAIT(0);
        __syncthreads();
        float acc[2][8][4];
        #pragma unroll
        for (int a = 0; a < 2; ++a)
            #pragma unroll
            for (int n = 0; n < 8; ++n)
                #pragma unroll
                for (int j = 0; j < 4; ++j) acc[a][n][j] = 0.f;
        u32 bofs = (u32)(buf * 128 * MPAD * 2);
        #pragma unroll
        for (int s = 0; s < 4; ++s) {
            int colb = (s * 16 + (lane >> 4) * 8) * 2;
            u32 fa[2][4], fal[2][4];
            #pragma unroll
            for (int a = 0; a < 2; ++a) {
                u32 ro = (u32)((wm * 32 + a * 16 + (lane & 15)) * MPAD * 2) + colb;
                LDM4(fa[a],  sQh + ro);
                LDM4(fal[a], sQl + ro);
            }
            u32 fbh[4][4], fbl[4][4];
            #pragma unroll
            for (int p = 0; p < 4; ++p) {
                u32 ro = (u32)((wn * 64 + p * 16 + (lane & 15)) * MPAD * 2) + colb + bofs;
                LDM4(fbh[p], sKh + ro);
                LDM4(fbl[p], sKl + ro);
            }
            #pragma unroll
            for (int a = 0; a < 2; ++a)
                #pragma unroll
                for (int p = 0; p < 4; ++p) {
                    MMA(acc[a][2*p],   fa[a],  fbh[p][0], fbh[p][2]);
                    MMA(acc[a][2*p+1], fa[a],  fbh[p][1], fbh[p][3]);
                    MMA(acc[a][2*p],   fa[a],  fbl[p][0], fbl[p][2]);
                    MMA(acc[a][2*p+1], fa[a],  fbl[p][1], fbl[p][3]);
                    MMA(acc[a][2*p],   fal[a], fbh[p][0], fbh[p][2]);
                    MMA(acc[a][2*p+1], fal[a], fbh[p][1], fbh[p][3]);
                }
        }
        #pragma unroll
        for (int a = 0; a < 2; ++a)
            #pragma unroll
            for (int n = 0; n < 8; ++n) {
                rmax[a][0] = fmaxf(rmax[a][0], fmaxf(acc[a][n][0], acc[a][n][1]));
                rmax[a][1] = fmaxf(rmax[a][1], fmaxf(acc[a][n][2], acc[a][n][3]));
            }
        __syncthreads();
    }

    // reduce within row-quads (lanes sharing lane>>2)
    #pragma unroll
    for (int a = 0; a < 2; ++a)
        #pragma unroll
        for (int hf = 0; hf < 2; ++hf) {
            float v = rmax[a][hf];
            v = fmaxf(v, __shfl_xor_sync(0xffffffffu, v, 1));
            v = fmaxf(v, __shfl_xor_sync(0xffffffffu, v, 2));
            rmax[a][hf] = v;
        }
    if ((lane & 3) == 0) {
        #pragma unroll
        for (int a = 0; a < 2; ++a)
            #pragma unroll
            for (int hf = 0; hf < 2; ++hf)
                red[wn * 128 + wm * 32 + a * 16 + hf * 8 + (lane >> 2)] = rmax[a][hf];
    }
    __syncthreads();
    if (tid < 128) {
        float m = fmaxf(red[tid], red[128 + tid]);
        const float* ks = ksum + bh * DH;
        float dot = 0.f;
        #pragma unroll
        for (int d = 0; d < 64; ++d)
            dot += (__bfloat162float(pQh[tid * MPAD + d]) +
                    __bfloat162float(pQl[tid * MPAD + d])) * ks[d];
        Mout[bh * LL + q0 + tid] = (m - dot * (1.f / LL)) * SCALE;
    }
}

// ===================== per-(b,h) sums ======================================
__global__ void sums_kernel(const float* __restrict__ k, const float* __restrict__ v,
                            float* __restrict__ ksum, float* __restrict__ vmean) {
    int bh = blockIdx.x, tid = threadIdx.x;
    int d = tid & 63, c = tid >> 6;
    const float* kb = k + (size_t)bh * LL * DH + d;
    const float* vb = v + (size_t)bh * LL * DH + d;
    float ks = 0.f, vs = 0.f;
    for (int l = c; l < LL; l += 4) { ks += kb[(size_t)l*DH]; vs += vb[(size_t)l*DH]; }
    __shared__ float rk[4][64], rv[4][64];
    rk[c][d] = ks; rv[c][d] = vs;
    __syncthreads();
    if (tid < 64) {
        float a = rk[0][tid] + rk[1][tid] + rk[2][tid] + rk[3][tid];
        float m = rv[0][tid] + rv[1][tid] + rv[2][tid] + rv[3][tid];
        ksum [bh*DH + tid] = a;
        vmean[bh*DH + tid] = m * (1.f / LL);
    }
}

// ===================== top-U selection =====================================
__global__ void topk_kernel(const float* __restrict__ M, int* __restrict__ idxout) {
    int bh = blockIdx.x, tid = threadIdx.x;
    __shared__ float sm[LL];
    __shared__ float bvv[256];
    __shared__ int   bii[256];
    for (int l = tid; l < LL; l += 256) sm[l] = M[bh*LL + l];
    __syncthreads();
    for (int it = 0; it < UU; ++it) {
        float best = -INFINITY; int bidx = LL;
        for (int l = tid; l < LL; l += 256) {
            float v = sm[l];
            if (v > best || (v == best && l < bidx)) { best = v; bidx = l; }
        }
        bvv[tid] = best; bii[tid] = bidx;
        __syncthreads();
        for (int s = 128; s > 0; s >>= 1) {
            if (tid < s) {
                if (bvv[tid+s] > bvv[tid] || (bvv[tid+s] == bvv[tid] && bii[tid+s] < bii[tid])) {
                    bvv[tid] = bvv[tid+s]; bii[tid] = bii[tid+s];
                }
            }
            __syncthreads();
        }
        if (tid == 0) { idxout[bh*UU + it] = bii[0]; sm[bii[0]] = -INFINITY; }
        __syncthreads();
    }
}

// ===================== attention (8 queries / block) =======================
__global__ __launch_bounds__(256, 2)
void attn_kernel(const float* __restrict__ q, const float* __restrict__ k,
                 const float* __restrict__ v, const int* __restrict__ idx,
                 float* __restrict__ upd) {
    extern __shared__ float sbuf[];
    float* sc   = sbuf;
    float* qv   = sbuf + 8*2048;
    float* red  = qv + 512;
    float* sinv = red + 2048;
    int bh = blockIdx.x, u0 = blockIdx.y * 8;
    int tid = threadIdx.x;
    const float* kb = k + (size_t)bh * LL * DH;
    const float* vb = v + (size_t)bh * LL * DH;

    for (int i = tid; i < 8*64; i += 256) {
        int u = i >> 6, d = i & 63;
        int lq = idx[bh*UU + u0 + u];
        qv[i] = q[((size_t)bh*LL + lq)*DH + d];
    }
    __syncthreads();

    for (int l = tid; l < LL; l += 256) {
        const float4* kr = (const float4*)(kb + (size_t)l*DH);
        float acc[8];
        #pragma unroll
        for (int u = 0; u < 8; ++u) acc[u] = 0.f;
        #pragma unroll
        for (int t = 0; t < 16; ++t) {
            float4 kv = kr[t];
            #pragma unroll
            for (int u = 0; u < 8; ++u) {
                float4 qq = *(const float4*)&qv[u*64 + t*4];
                acc[u] += kv.x*qq.x + kv.y*qq.y + kv.z*qq.z + kv.w*qq.w;
            }
        }
        #pragma unroll
        for (int u = 0; u < 8; ++u) sc[u*2048 + l] = acc[u] * SCALE;
    }
    __syncthreads();

    {
        int u = tid >> 5, lane = tid & 31;
        float m = -INFINITY;
        for (int l = lane; l < LL; l += 32) m = fmaxf(m, sc[u*2048 + l]);
        #pragma unroll
        for (int o = 16; o > 0; o >>= 1) m = fmaxf(m, __shfl_xor_sync(0xffffffffu, m, o));
        float s = 0.f;
        for (int l = lane; l < LL; l += 32) {
            float e = __expf(sc[u*2048 + l] - m);
            sc[u*2048 + l] = e; s += e;
        }
        #pragma unroll
        for (int o = 16; o > 0; o >>= 1) s += __shfl_xor_sync(0xffffffffu, s, o);
        if (lane == 0) sinv[u] = 1.f / s;
    }
    __syncthreads();

    int d = tid & 63, lc = tid >> 6;
    float acc[8];
    #pragma unroll
    for (int u = 0; u < 8; ++u) acc[u] = 0.f;
    for (int l = lc; l < LL; l += 4) {
        float vv = vb[(size_t)l*DH + d];
        #pragma unroll
        for (int u = 0; u < 8; ++u) acc[u] += sc[u*2048 + l] * vv;
    }
    #pragma unroll
    for (int u = 0; u < 8; ++u) red[(lc*8 + u)*64 + d] = acc[u];
    __syncthreads();
    if (tid < 64) {
        #pragma unroll
        for (int u = 0; u < 8; ++u) {
            float t = red[u*64 + tid] + red[(8+u)*64 + tid] +
                      red[(16+u)*64 + tid] + red[(24+u)*64 + tid];
            upd[((size_t)bh*UU + u0 + u)*DH + tid] = t * sinv[u];
        }
    }
}

// ===================== Wo via base + sparse corrections ====================
__global__ void base_kernel(const float* __restrict__ vmean, const float* __restrict__ Wo,
                            const float* __restrict__ bo, float* __restrict__ base) {
    int b = blockIdx.x, n = threadIdx.x;
    const float* vm = vmean + b * 512;
    float acc = bo[n];
    for (int kk = 0; kk < 512; ++kk)
        acc += vm[kk] * Wo[(size_t)kk*512 + n];
    base[b*512 + n] = acc;
}

__global__ void corr_kernel(const float* __restrict__ upd, const float* __restrict__ vmean,
                            const float* __restrict__ Wo, const int* __restrict__ idx,
                            float* __restrict__ delta) {
    int blk = blockIdx.x;
    int bh = blk / UU, u = blk % UU;
    int h = bh & 7, b = bh >> 3;
    __shared__ float du[64];
    int tid = threadIdx.x;
    if (tid < 64) du[tid] = upd[(size_t)blk*64 + tid] - vmean[bh*64 + tid];
    __syncthreads();
    int l = idx[bh*UU + u];
    float* drow = delta + ((size_t)b*LL + l)*DD;
    const float* wrow = Wo + (size_t)h*64*512;
    #pragma unroll
    for (int half = 0; half < 2; ++half) {
        int n = tid + half*256;
        float acc = 0.f;
        #pragma unroll 8
        for (int d = 0; d < 64; ++d) acc += du[d] * wrow[(size_t)d*512 + n];
        atomicAdd(&drow[n], acc);
    }
}

// ===================== residual + LayerNorm ================================
__global__ void addln_base_kernel(float* h, const float* __restrict__ delta,
                                  const float* __restrict__ base,
                                  const float* __restrict__ g, const float* __restrict__ b) {
    int row = blockIdx.x, tid = threadIdx.x;
    int bb_ = row >> 11;
    float* hr = h + (size_t)row * DD;
    const float* dr = delta + (size_t)row * DD;
    const float* br = base + bb_ * DD;
    __shared__ float rbuf[8];
    __shared__ float sh_mean, sh_var;
    float s0 = hr[tid]       + dr[tid]       + br[tid];
    float s1 = hr[tid + 256] + dr[tid + 256] + br[tid + 256];
    float s = s0 + s1;
    for (int o = 16; o > 0; o >>= 1) s += __shfl_down_sync(0xffffffffu, s, o);
    if ((tid & 31) == 0) rbuf[tid >> 5] = s;
    __syncthreads();
    if (tid == 0) {
        float t = 0.f;
        #pragma unroll
        for (int i = 0; i < 8; ++i) t += rbuf[i];
        sh_mean = t * (1.f / DD);
    }
    __syncthreads();
    float mval = sh_mean;
    float d0 = s0 - mval, d1 = s1 - mval;
    float vv = d0*d0 + d1*d1;
    for (int o = 16; o > 0; o >>= 1) vv += __shfl_down_sync(0xffffffffu, vv, o);
    if ((tid & 31) == 0) rbuf[tid >> 5] = vv;
    __syncthreads();
    if (tid == 0) {
        float t = 0.f;
        #pragma unroll
        for (int i = 0; i < 8; ++i) t += rbuf[i];
        sh_var = t * (1.f / DD);
    }
    __syncthreads();
    float inv = rsqrtf(sh_var + 1e-5f);
    hr[tid]       = d0 * inv * g[tid]       + b[tid];
    hr[tid + 256] = d1 * inv * g[tid + 256] + b[tid + 256];
}

__global__ void addln_kernel(float* h, const float* __restrict__ a,
                             const float* __restrict__ g, const float* __restrict__ b) {
    int row = blockIdx.x, tid = threadIdx.x;
    float* hr = h + (size_t)row * DD;
    const float* ar = a + (size_t)row * DD;
    __shared__ float rbuf[8];
    __shared__ float sh_mean, sh_var;
    float s0 = hr[tid]       + ar[tid];
    float s1 = hr[tid + 256] + ar[tid + 256];
    float s = s0 + s1;
    for (int o = 16; o > 0; o >>= 1) s += __shfl_down_sync(0xffffffffu, s, o);
    if ((tid & 31) == 0) rbuf[tid >> 5] = s;
    __syncthreads();
    if (tid == 0) {
        float t = 0.f;
        #pragma unroll
        for (int i = 0; i < 8; ++i) t += rbuf[i];
        sh_mean = t * (1.f / DD);
    }
    __syncthreads();
    float mval = sh_mean;
    float d0 = s0 - mval, d1 = s1 - mval;
    float vv = d0*d0 + d1*d1;
    for (int o = 16; o > 0; o >>= 1) vv += __shfl_down_sync(0xffffffffu, vv, o);
    if ((tid & 31) == 0) rbuf[tid >> 5] = vv;
    __syncthreads();
    if (tid == 0) {
        float t = 0.f;
        #pragma unroll
        for (int i = 0; i < 8; ++i) t += rbuf[i];
        sh_var = t * (1.f / DD);
    }
    __syncthreads();
    float inv = rsqrtf(sh_var + 1e-5f);
    hr[tid]       = d0 * inv * g[tid]       + b[tid];
    hr[tid + 256] = d1 * inv * g[tid + 256] + b[tid + 256];
}

// ===================== final projection ====================================
__global__ void proj_kernel(const float* __restrict__ h, const float* __restrict__ pw,
                            const float* __restrict__ pb, float* __restrict__ out) {
    int bp = blockIdx.x;
    int b = bp / PP, p = bp % PP;
    int l = LL - PP + p;
    int tid = threadIdx.x;
    const float* hr = h + ((size_t)b*LL + l)*DD;
    float acc[EE];
    #pragma unroll
    for (int e = 0; e < EE; ++e) acc[e] = 0.f;
    for (int kk = tid; kk < DD; kk += 64) {
        float hv = hr[kk];
        #pragma unroll
        for (int e = 0; e < EE; ++e) acc[e] += hv * pw[kk*EE + e];
    }
    __shared__ float red[EE][64];
    #pragma unroll
    for (int e = 0; e < EE; ++e) red[e][tid] = acc[e];
    __syncthreads();
    if (tid < EE) {
        float t = 0.f;
        for (int i = 0; i < 64; ++i) t += red[tid][i];
        out[(size_t)bp * EE + tid] = t + pb[tid];
    }
}

// ===================== host driver =========================================
#define SMEM_G_BYTES (4 * GARR * 2)                       // 81920
#define SMEM_M_BYTES ((2*128*MPAD + 4*128*MPAD) * 2 + 1024)
#define SMEM_A_BYTES ((8*2048 + 512 + 2048 + 8) * 4)

extern "C" void kernel_launch(void* const* d_in, const int* in_sizes, int n_in,
                              void* d_out, int out_size) {
    const float* x      = (const float*)d_in[0];
    const float* emb_w  = (const float*)d_in[1];
    const float* emb_b  = (const float*)d_in[2];
    const float* Wq     = (const float*)d_in[3];
    const float* bq     = (const float*)d_in[4];
    const float* Wk     = (const float*)d_in[5];
    const float* bk     = (const float*)d_in[6];
    const float* Wv     = (const float*)d_in[7];
    const float* bv     = (const float*)d_in[8];
    const float* Wo     = (const float*)d_in[9];
    const float* bo     = (const float*)d_in[10];
    const float* W1     = (const float*)d_in[11];
    const float* b1     = (const float*)d_in[12];
    const float* W2     = (const float*)d_in[13];
    const float* b2     = (const float*)d_in[14];
    const float* ln1_g  = (const float*)d_in[15];
    const float* ln1_b  = (const float*)d_in[16];
    const float* ln2_g  = (const float*)d_in[17];
    const float* ln2_b  = (const float*)d_in[18];
    const float* proj_w = (const float*)d_in[19];
    const float* proj_b = (const float*)d_in[20];

    static float *p_h = nullptr, *p_q, *p_k, *p_v, *p_t1, *p_t2, *p_M,
                 *p_ksum, *p_vmean, *p_upd, *p_base;
    static bf16 *p_ah, *p_al, *p_wh, *p_wl, *p_qh, *p_ql, *p_kh, *p_kl;
    static int *p_idx;
    if (!p_h) {
        cudaGetSymbolAddress((void**)&p_h,    g_h);
        cudaGetSymbolAddress((void**)&p_q,    g_q);
        cudaGetSymbolAddress((void**)&p_k,    g_k);
        cudaGetSymbolAddress((void**)&p_v,    g_v);
        cudaGetSymbolAddress((void**)&p_t1,   g_t1);
        cudaGetSymbolAddress((void**)&p_t2,   g_t2);
        cudaGetSymbolAddress((void**)&p_M,    g_M);
        cudaGetSymbolAddress((void**)&p_idx,  g_idx);
        cudaGetSymbolAddress((void**)&p_ksum, g_ksum);
        cudaGetSymbolAddress((void**)&p_vmean,g_vmean);
        cudaGetSymbolAddress((void**)&p_upd,  g_upd);
        cudaGetSymbolAddress((void**)&p_base, g_base);
        cudaGetSymbolAddress((void**)&p_ah,   g_ah);
        cudaGetSymbolAddress((void**)&p_al,   g_al);
        cudaGetSymbolAddress((void**)&p_wh,   g_wh);
        cudaGetSymbolAddress((void**)&p_wl,   g_wl);
        cudaGetSymbolAddress((void**)&p_qh,   g_qh);
        cudaGetSymbolAddress((void**)&p_ql,   g_ql);
        cudaGetSymbolAddress((void**)&p_kh,   g_kh);
        cudaGetSymbolAddress((void**)&p_kl,   g_kl);
        cudaFuncSetAttribute(gemm_mma<0>, cudaFuncAttributeMaxDynamicSharedMemorySize, SMEM_G_BYTES);
        cudaFuncSetAttribute(gemm_mma<1>, cudaFuncAttributeMaxDynamicSharedMemorySize, SMEM_G_BYTES);
        cudaFuncSetAttribute(gemm_mma<2>, cudaFuncAttributeMaxDynamicSharedMemorySize, SMEM_G_BYTES);
        cudaFuncSetAttribute(m_mma,       cudaFuncAttributeMaxDynamicSharedMemorySize, SMEM_M_BYTES);
        cudaFuncSetAttribute(attn_kernel, cudaFuncAttributeMaxDynamicSharedMemorySize, SMEM_A_BYTES);
    }

    embed_kernel<<<(BB*LL*DD)/256, 256>>>(x, emb_w, emb_b, p_h);

    dim3 gg(MROWS/128, DD/128);
    dim3 wsg(16, 16, 5), wsb(32, 8);
    const int NSPLIT  = (MROWS*DD/4)/256;     // h/t1 splits
    const int NSPLITQ = (BH*LL*DH/4)/256;     // q/k splits
    for (int il = 0; il < NL; ++il) {
        const size_t wo = (size_t)il * DD * DD;
        const size_t boff = (size_t)il * DD;
        wsplit_kernel<<<wsg, wsb>>>(Wq + wo, Wk + wo, Wv + wo, W1 + wo, W2 + wo, p_wh, p_wl);
        split_kernel<<<NSPLIT, 256>>>(p_h, p_ah, p_al);
        gemm_mma<2><<<gg, 256, SMEM_G_BYTES>>>(p_ah, p_al, p_wh + 0*DD*DD, p_wl + 0*DD*DD, bq + boff, p_q);
        gemm_mma<2><<<gg, 256, SMEM_G_BYTES>>>(p_ah, p_al, p_wh + 1*DD*DD, p_wl + 1*DD*DD, bk + boff, p_k);
        gemm_mma<2><<<gg, 256, SMEM_G_BYTES>>>(p_ah, p_al, p_wh + 2*DD*DD, p_wl + 2*DD*DD, bv + boff, p_v);
        sums_kernel<<<BH, 256>>>(p_k, p_v, p_ksum, p_vmean);
        split_kernel<<<NSPLITQ, 256>>>(p_q, p_qh, p_ql);
        split_kernel<<<NSPLITQ, 256>>>(p_k, p_kh, p_kl);
        m_mma<<<dim3(LL/128, BH), 256, SMEM_M_BYTES>>>(p_qh, p_ql, p_kh, p_kl, p_ksum, p_M);
        topk_kernel<<<BH, 256>>>(p_M, p_idx);
        attn_kernel<<<dim3(BH, UU/8), 256, SMEM_A_BYTES>>>(p_q, p_k, p_v, p_idx, p_upd);
        base_kernel<<<BB, 512>>>(p_vmean, Wo + wo, bo + boff, p_base);
        cudaMemsetAsync(p_t2, 0, (size_t)BB*LL*DD*sizeof(float));
        corr_kernel<<<BH*UU, 256>>>(p_upd, p_vmean, Wo + wo, p_idx, p_t2);
        addln_base_kernel<<<MROWS, 256>>>(p_h, p_t2, p_base, ln1_g + boff, ln1_b + boff);
        split_kernel<<<NSPLIT, 256>>>(p_h, p_ah, p_al);
        gemm_mma<1><<<gg, 256, SMEM_G_BYTES>>>(p_ah, p_al, p_wh + 3*DD*DD, p_wl + 3*DD*DD, b1 + boff, p_t1);
        split_kernel<<<NSPLIT, 256>>>(p_t1, p_ah, p_al);
        gemm_mma<0><<<gg, 256, SMEM_G_BYTES>>>(p_ah, p_al, p_wh + 4*DD*DD, p_wl + 4*DD*DD, b2 + boff, p_t2);
        addln_kernel<<<MROWS, 256>>>(p_h, p_t2, ln2_g + boff, ln2_b + boff);
    }

    proj_kernel<<<BB*PP, 64>>>(p_h, proj_w, proj_b, (float*)d_out);
}

// round 13
// speedup vs baseline: 2.3278x; 1.1928x over previous
#include <cuda_runtime.h>
#include <cuda_bf16.h>
#include <math.h>
#include <stdint.h>

#define BB   4
#define LL   2048
#define EE   7
#define DD   512
#define HH   8
#define DH   64
#define PP   720
#define NL   2
#define UU   40
#define BH   (BB*HH)
#define MROWS (BB*LL)
#define SCALE 0.125f

typedef unsigned long long ull;
typedef uint32_t u32;
typedef __nv_bfloat16 bf16;

// ===================== warp-MMA helpers (sm_80 baseline PTX) ================
__device__ __forceinline__ u32 smem_u32(const void* p) {
    u32 a;
    asm("{ .reg .u64 t; cvta.to.shared.u64 t, %1; cvt.u32.u64 %0, t; }"
        : "=r"(a) : "l"(p));
    return a;
}
__device__ __forceinline__ void cpasync16(u32 dst, const void* src) {
    asm volatile("cp.async.cg.shared.global [%0], [%1], 16;" :: "r"(dst), "l"(src));
}
#define CP_COMMIT() asm volatile("cp.async.commit_group;" ::: "memory")
#define CP_WAIT(n)  asm volatile("cp.async.wait_group %0;" :: "n"(n) : "memory")

#define LDM4(f, addr) \
    asm volatile("ldmatrix.sync.aligned.m8n8.x4.shared.b16 {%0,%1,%2,%3}, [%4];" \
        : "=r"((f)[0]), "=r"((f)[1]), "=r"((f)[2]), "=r"((f)[3]) : "r"(addr))

#define MMA(c, a, b0, b1) \
    asm volatile("mma.sync.aligned.m16n8k16.row.col.f32.bf16.bf16.f32 " \
        "{%0,%1,%2,%3}, {%4,%5,%6,%7}, {%8,%9}, {%0,%1,%2,%3};" \
        : "+f"((c)[0]), "+f"((c)[1]), "+f"((c)[2]), "+f"((c)[3]) \
        : "r"((a)[0]), "r"((a)[1]), "r"((a)[2]), "r"((a)[3]), "r"(b0), "r"(b1))

// ===================== scratch =============================================
__device__ float g_h [BB*LL*DD];
__device__ float g_q [BH*LL*DH];
__device__ float g_k [BH*LL*DH];
__device__ float g_v [BH*LL*DH];
__device__ float g_t1[BB*LL*DD];
__device__ float g_t2[BB*LL*DD];
__device__ float g_M [BH*LL];
__device__ int   g_idx[BH*UU];
__device__ float g_ksum [BH*DH];
__device__ float g_vmean[BH*DH];
__device__ float g_upd[BH*UU*DH];
__device__ float g_base[BB*DD];
__device__ bf16 g_ah[MROWS*DD];
__device__ bf16 g_al[MROWS*DD];
__device__ bf16 g_wh[5*DD*DD];
__device__ bf16 g_wl[5*DD*DD];
__device__ bf16 g_qh[BH*LL*DH];
__device__ bf16 g_kh[BH*LL*DH];

// ===================== conversions =========================================
__global__ void split_kernel(const float* __restrict__ in,
                             bf16* __restrict__ hi, bf16* __restrict__ lo) {
    int i = blockIdx.x * 256 + threadIdx.x;       // over N/4
    float4 f = ((const float4*)in)[i];
    __nv_bfloat162 h0 = __floats2bfloat162_rn(f.x, f.y);
    __nv_bfloat162 h1 = __floats2bfloat162_rn(f.z, f.w);
    float2 h0f = __bfloat1622float2(h0), h1f = __bfloat1622float2(h1);
    __nv_bfloat162 l0 = __floats2bfloat162_rn(f.x - h0f.x, f.y - h0f.y);
    __nv_bfloat162 l1 = __floats2bfloat162_rn(f.z - h1f.x, f.w - h1f.y);
    ((uint2*)hi)[i] = make_uint2(*(u32*)&h0, *(u32*)&h1);
    ((uint2*)lo)[i] = make_uint2(*(u32*)&l0, *(u32*)&l1);
}

// W [k][n] fp32 -> Wt [n][k] bf16 hi/lo; 5 weight slots via blockIdx.z
__global__ void wsplit_kernel(const float* __restrict__ Wq, const float* __restrict__ Wk,
                              const float* __restrict__ Wv, const float* __restrict__ W1,
                              const float* __restrict__ W2,
                              bf16* __restrict__ wh, bf16* __restrict__ wl) {
    int slot = blockIdx.z;
    const float* W = (slot == 0) ? Wq : (slot == 1) ? Wk : (slot == 2) ? Wv
                   : (slot == 3) ? W1 : W2;
    __shared__ float ts[32][33];
    int n0 = blockIdx.x * 32, k0 = blockIdx.y * 32;
    int tx = threadIdx.x, ty = threadIdx.y;      // (32, 8)
    #pragma unroll
    for (int i = 0; i < 4; ++i)
        ts[ty + i*8][tx] = W[(size_t)(k0 + ty + i*8) * 512 + n0 + tx];
    __syncthreads();
    size_t so = (size_t)slot * DD * DD;
    #pragma unroll
    for (int i = 0; i < 4; ++i) {
        float v = ts[tx][ty + i*8];
        bf16 h = __float2bfloat16(v);
        bf16 l = __float2bfloat16(v - __bfloat162float(h));
        size_t o = so + (size_t)(n0 + ty + i*8) * 512 + k0 + tx;
        wh[o] = h; wl[o] = l;
    }
}

// ===================== embedding ===========================================
__global__ void embed_kernel(const float* __restrict__ x,
                             const float* __restrict__ w,
                             const float* __restrict__ b,
                             float* __restrict__ out) {
    int i = blockIdx.x * 256 + threadIdx.x;
    int row = i >> 9, n = i & 511;
    float acc = b[n];
    #pragma unroll
    for (int e = 0; e < EE; ++e) acc += x[row*EE + e] * w[e*DD + n];
    out[i] = acc;
}

// ===================== warp-MMA GEMM [8192,512]x[512,512] ===================
// MODE 0: plain; 1: relu; 2: head scatter; 3: head scatter + bf16-hi copy
#define GK 32
#define GPAD 40
#define GARR (2*128*GPAD)
template<int MODE>
__global__ __launch_bounds__(256, 2)
void gemm_mma(const bf16* __restrict__ ah, const bf16* __restrict__ al,
              const bf16* __restrict__ wh, const bf16* __restrict__ wl,
              const float* __restrict__ bias, float* __restrict__ out,
              bf16* __restrict__ outh) {
    extern __shared__ bf16 sm[];
    bf16* pAh = sm;
    bf16* pAl = pAh + GARR;
    bf16* pBh = pAl + GARR;
    bf16* pBl = pBh + GARR;
    const int tid = threadIdx.x, lane = tid & 31, wid = tid >> 5;
    const int wm = wid & 3, wn = wid >> 2;
    const int m0 = blockIdx.x * 128, n0 = blockIdx.y * 128;

    const u32 sAh = smem_u32(pAh), sAl = smem_u32(pAl);
    const u32 sBh = smem_u32(pBh), sBl = smem_u32(pBl);

    float acc[2][8][4];
    #pragma unroll
    for (int a = 0; a < 2; ++a)
        #pragma unroll
        for (int n = 0; n < 8; ++n)
            #pragma unroll
            for (int j = 0; j < 4; ++j) acc[a][n][j] = 0.f;

    auto load_chunk = [&](int c, int buf) {
        int kb = c * GK;
        #pragma unroll
        for (int u = 0; u < 2; ++u) {
            int i = tid + u * 256;
            int r = i >> 2, j = (i & 3) * 8;
            u32 doff = (u32)((buf * 128 * GPAD + r * GPAD + j) * 2);
            cpasync16(sAh + doff, ah + (size_t)(m0 + r) * 512 + kb + j);
            cpasync16(sAl + doff, al + (size_t)(m0 + r) * 512 + kb + j);
            cpasync16(sBh + doff, wh + (size_t)(n0 + r) * 512 + kb + j);
            cpasync16(sBl + doff, wl + (size_t)(n0 + r) * 512 + kb + j);
        }
        CP_COMMIT();
    };

    load_chunk(0, 0);
    for (int c = 0; c < 16; ++c) {
        int buf = c & 1;
        if (c < 15) load_chunk(c + 1, buf ^ 1);
        if (c < 15) CP_WAIT(1); else CP_WAIT(0);
        __syncthreads();
        u32 bofs = (u32)(buf * 128 * GPAD * 2);
        #pragma unroll
        for (int s = 0; s < 2; ++s) {
            int colb = (s * 16 + (lane >> 4) * 8) * 2;
            u32 fa[2][4], fal[2][4];
            #pragma unroll
            for (int a = 0; a < 2; ++a) {
                u32 ro = (u32)((wm * 32 + a * 16 + (lane & 15)) * GPAD * 2) + colb + bofs;
                LDM4(fa[a],  sAh + ro);
                LDM4(fal[a], sAl + ro);
            }
            #pragma unroll
            for (int p = 0; p < 4; ++p) {
                u32 fbh[4], fbl[4];
                u32 ro = (u32)((wn * 64 + p * 16 + (lane & 15)) * GPAD * 2) + colb + bofs;
                LDM4(fbh, sBh + ro);
                LDM4(fbl, sBl + ro);
                #pragma unroll
                for (int a = 0; a < 2; ++a) {
                    MMA(acc[a][2*p],   fa[a],  fbh[0], fbh[2]);
                    MMA(acc[a][2*p+1], fa[a],  fbh[1], fbh[3]);
                    MMA(acc[a][2*p],   fa[a],  fbl[0], fbl[2]);
                    MMA(acc[a][2*p+1], fa[a],  fbl[1], fbl[3]);
                    MMA(acc[a][2*p],   fal[a], fbh[0], fbh[2]);
                    MMA(acc[a][2*p+1], fal[a], fbh[1], fbh[3]);
                }
            }
        }
        __syncthreads();
    }

    int rg = m0 + wm * 32 + (lane >> 2);
    int cg = n0 + wn * 64 + (lane & 3) * 2;
    #pragma unroll
    for (int a = 0; a < 2; ++a)
        #pragma unroll
        for (int n = 0; n < 8; ++n) {
            int col = cg + n * 8;
            float2 bv = *(const float2*)&bias[col];
            #pragma unroll
            for (int hf = 0; hf < 2; ++hf) {
                int row = rg + a * 16 + hf * 8;
                float2 v = make_float2(acc[a][n][hf*2] + bv.x, acc[a][n][hf*2+1] + bv.y);
                if (MODE == 1) { v.x = fmaxf(v.x, 0.f); v.y = fmaxf(v.y, 0.f); }
                if (MODE >= 2) {
                    int hh = col >> 6, dh = col & 63, b_ = row >> 11, l_ = row & 2047;
                    size_t o = (((size_t)(b_*HH + hh))*LL + l_)*DH + dh;
                    *(float2*)&out[o] = v;
                    if (MODE == 3) {
                        __nv_bfloat162 hv = __floats2bfloat162_rn(v.x, v.y);
                        *(u32*)&outh[o] = *(u32*)&hv;
                    }
                } else {
                    *(float2*)&out[(size_t)row * 512 + col] = v;
                }
            }
        }
}

// ===================== M(q): 1-term bf16 warp MMA ==========================
// scores tile 128q x 128k, K-dim 64; Q fragments hoisted to registers
#define MPAD 72
__global__ __launch_bounds__(256, 2)
void m_mma(const bf16* __restrict__ qh, const bf16* __restrict__ kh,
           const float* __restrict__ qf, const float* __restrict__ ksum,
           float* __restrict__ Mout) {
    extern __shared__ bf16 sm[];
    bf16* pQ = sm;                          // 128*MPAD
    bf16* pK = pQ + 128*MPAD;               // 2 buffers
    float* red = (float*)(pK + 2*128*MPAD); // [2][128]
    const int tid = threadIdx.x, lane = tid & 31, wid = tid >> 5;
    const int wm = wid & 3, wn = wid >> 2;
    const int bh = blockIdx.y, q0 = blockIdx.x * 128;
    const bf16* qhb = qh + (size_t)bh * LL * DH;
    const bf16* khb = kh + (size_t)bh * LL * DH;
    const u32 sQ = smem_u32(pQ), sK = smem_u32(pK);

    #pragma unroll
    for (int u = 0; u < 4; ++u) {
        int i = tid + u * 256;
        int r = i >> 3, j = (i & 7) * 8;
        cpasync16(sQ + (u32)((r * MPAD + j) * 2), qhb + (size_t)(q0 + r) * 64 + j);
    }
    CP_COMMIT();

    auto load_k = [&](int t, int buf) {
        #pragma unroll
        for (int u = 0; u < 4; ++u) {
            int i = tid + u * 256;
            int r = i >> 3, j = (i & 7) * 8;
            cpasync16(sK + (u32)((buf * 128 * MPAD + r * MPAD + j) * 2),
                      khb + (size_t)(t * 128 + r) * 64 + j);
        }
        CP_COMMIT();
    };
    load_k(0, 0);

    CP_WAIT(1);
    __syncthreads();
    // hoist Q fragments: 4 k-slices x 2 row-halves
    u32 fq[4][2][4];
    #pragma unroll
    for (int s = 0; s < 4; ++s) {
        int colb = (s * 16 + (lane >> 4) * 8) * 2;
        #pragma unroll
        for (int a = 0; a < 2; ++a) {
            u32 ro = (u32)((wm * 32 + a * 16 + (lane & 15)) * MPAD * 2) + colb;
            LDM4(fq[s][a], sQ + ro);
        }
    }

    float rmax[2][2];
    rmax[0][0] = rmax[0][1] = rmax[1][0] = rmax[1][1] = -INFINITY;

    for (int t = 0; t < 16; ++t) {
        int buf = t & 1;
        if (t < 15) load_k(t + 1, buf ^ 1);
        if (t < 15) CP_WAIT(1); else CP_WAIT(0);
        __syncthreads();
        float acc[2][8][4];
        #pragma unroll
        for (int a = 0; a < 2; ++a)
            #pragma unroll
            for (int n = 0; n < 8; ++n)
                #pragma unroll
                for (int j = 0; j < 4; ++j) acc[a][n][j] = 0.f;
        u32 bofs = (u32)(buf * 128 * MPAD * 2);
        #pragma unroll
        for (int s = 0; s < 4; ++s) {
            int colb = (s * 16 + (lane >> 4) * 8) * 2;
            #pragma unroll
            for (int p = 0; p < 4; ++p) {
                u32 fb[4];
                u32 ro = (u32)((wn * 64 + p * 16 + (lane & 15)) * MPAD * 2) + colb + bofs;
                LDM4(fb, sK + ro);
                #pragma unroll
                for (int a = 0; a < 2; ++a) {
                    MMA(acc[a][2*p],   fq[s][a], fb[0], fb[2]);
                    MMA(acc[a][2*p+1], fq[s][a], fb[1], fb[3]);
                }
            }
        }
        #pragma unroll
        for (int a = 0; a < 2; ++a)
            #pragma unroll
            for (int n = 0; n < 8; ++n) {
                rmax[a][0] = fmaxf(rmax[a][0], fmaxf(acc[a][n][0], acc[a][n][1]));
                rmax[a][1] = fmaxf(rmax[a][1], fmaxf(acc[a][n][2], acc[a][n][3]));
            }
        __syncthreads();
    }

    #pragma unroll
    for (int a = 0; a < 2; ++a)
        #pragma unroll
        for (int hf = 0; hf < 2; ++hf) {
            float v = rmax[a][hf];
            v = fmaxf(v, __shfl_xor_sync(0xffffffffu, v, 1));
            v = fmaxf(v, __shfl_xor_sync(0xffffffffu, v, 2));
            rmax[a][hf] = v;
        }
    if ((lane & 3) == 0) {
        #pragma unroll
        for (int a = 0; a < 2; ++a)
            #pragma unroll
            for (int hf = 0; hf < 2; ++hf)
                red[wn * 128 + wm * 32 + a * 16 + hf * 8 + (lane >> 2)] = rmax[a][hf];
    }
    __syncthreads();
    if (tid < 128) {
        float m = fmaxf(red[tid], red[128 + tid]);
        const float* ks = ksum + bh * DH;
        const float* qrow = qf + ((size_t)bh * LL + q0 + tid) * DH;
        float dot = 0.f;
        #pragma unroll
        for (int d = 0; d < 64; ++d) dot += qrow[d] * ks[d];
        Mout[bh * LL + q0 + tid] = (m - dot * (1.f / LL)) * SCALE;
    }
}

// ===================== per-(b,h) sums ======================================
__global__ void sums_kernel(const float* __restrict__ k, const float* __restrict__ v,
                            float* __restrict__ ksum, float* __restrict__ vmean) {
    int bh = blockIdx.x, tid = threadIdx.x;
    int d = tid & 63, c = tid >> 6;
    const float* kb = k + (size_t)bh * LL * DH + d;
    const float* vb = v + (size_t)bh * LL * DH + d;
    float ks = 0.f, vs = 0.f;
    for (int l = c; l < LL; l += 4) { ks += kb[(size_t)l*DH]; vs += vb[(size_t)l*DH]; }
    __shared__ float rk[4][64], rv[4][64];
    rk[c][d] = ks; rv[c][d] = vs;
    __syncthreads();
    if (tid < 64) {
        float a = rk[0][tid] + rk[1][tid] + rk[2][tid] + rk[3][tid];
        float m = rv[0][tid] + rv[1][tid] + rv[2][tid] + rv[3][tid];
        ksum [bh*DH + tid] = a;
        vmean[bh*DH + tid] = m * (1.f / LL);
    }
}

// ===================== top-U selection =====================================
__global__ void topk_kernel(const float* __restrict__ M, int* __restrict__ idxout) {
    int bh = blockIdx.x, tid = threadIdx.x;
    __shared__ float sm[LL];
    __shared__ float bvv[256];
    __shared__ int   bii[256];
    for (int l = tid; l < LL; l += 256) sm[l] = M[bh*LL + l];
    __syncthreads();
    for (int it = 0; it < UU; ++it) {
        float best = -INFINITY; int bidx = LL;
        for (int l = tid; l < LL; l += 256) {
            float v = sm[l];
            if (v > best || (v == best && l < bidx)) { best = v; bidx = l; }
        }
        bvv[tid] = best; bii[tid] = bidx;
        __syncthreads();
        for (int s = 128; s > 0; s >>= 1) {
            if (tid < s) {
                if (bvv[tid+s] > bvv[tid] || (bvv[tid+s] == bvv[tid] && bii[tid+s] < bii[tid])) {
                    bvv[tid] = bvv[tid+s]; bii[tid] = bii[tid+s];
                }
            }
            __syncthreads();
        }
        if (tid == 0) { idxout[bh*UU + it] = bii[0]; sm[bii[0]] = -INFINITY; }
        __syncthreads();
    }
}

// ===================== attention (8 queries / block) =======================
__global__ __launch_bounds__(256, 2)
void attn_kernel(const float* __restrict__ q, const float* __restrict__ k,
                 const float* __restrict__ v, const int* __restrict__ idx,
                 float* __restrict__ upd) {
    extern __shared__ float sbuf[];
    float* sc   = sbuf;
    float* qv   = sbuf + 8*2048;
    float* red  = qv + 512;
    float* sinv = red + 2048;
    int bh = blockIdx.x, u0 = blockIdx.y * 8;
    int tid = threadIdx.x;
    const float* kb = k + (size_t)bh * LL * DH;
    const float* vb = v + (size_t)bh * LL * DH;

    for (int i = tid; i < 8*64; i += 256) {
        int u = i >> 6, d = i & 63;
        int lq = idx[bh*UU + u0 + u];
        qv[i] = q[((size_t)bh*LL + lq)*DH + d];
    }
    __syncthreads();

    for (int l = tid; l < LL; l += 256) {
        const float4* kr = (const float4*)(kb + (size_t)l*DH);
        float acc[8];
        #pragma unroll
        for (int u = 0; u < 8; ++u) acc[u] = 0.f;
        #pragma unroll
        for (int t = 0; t < 16; ++t) {
            float4 kv = kr[t];
            #pragma unroll
            for (int u = 0; u < 8; ++u) {
                float4 qq = *(const float4*)&qv[u*64 + t*4];
                acc[u] += kv.x*qq.x + kv.y*qq.y + kv.z*qq.z + kv.w*qq.w;
            }
        }
        #pragma unroll
        for (int u = 0; u < 8; ++u) sc[u*2048 + l] = acc[u] * SCALE;
    }
    __syncthreads();

    {
        int u = tid >> 5, lane = tid & 31;
        float m = -INFINITY;
        for (int l = lane; l < LL; l += 32) m = fmaxf(m, sc[u*2048 + l]);
        #pragma unroll
        for (int o = 16; o > 0; o >>= 1) m = fmaxf(m, __shfl_xor_sync(0xffffffffu, m, o));
        float s = 0.f;
        for (int l = lane; l < LL; l += 32) {
            float e = __expf(sc[u*2048 + l] - m);
            sc[u*2048 + l] = e; s += e;
        }
        #pragma unroll
        for (int o = 16; o > 0; o >>= 1) s += __shfl_xor_sync(0xffffffffu, s, o);
        if (lane == 0) sinv[u] = 1.f / s;
    }
    __syncthreads();

    int d = tid & 63, lc = tid >> 6;
    float acc[8];
    #pragma unroll
    for (int u = 0; u < 8; ++u) acc[u] = 0.f;
    for (int l = lc; l < LL; l += 4) {
        float vv = vb[(size_t)l*DH + d];
        #pragma unroll
        for (int u = 0; u < 8; ++u) acc[u] += sc[u*2048 + l] * vv;
    }
    #pragma unroll
    for (int u = 0; u < 8; ++u) red[(lc*8 + u)*64 + d] = acc[u];
    __syncthreads();
    if (tid < 64) {
        #pragma unroll
        for (int u = 0; u < 8; ++u) {
            float t = red[u*64 + tid] + red[(8+u)*64 + tid] +
                      red[(16+u)*64 + tid] + red[(24+u)*64 + tid];
            upd[((size_t)bh*UU + u0 + u)*DH + tid] = t * sinv[u];
        }
    }
}

// ===================== Wo via base + sparse corrections ====================
__global__ void base_kernel(const float* __restrict__ vmean, const float* __restrict__ Wo,
                            const float* __restrict__ bo, float* __restrict__ base) {
    int b = blockIdx.x, n = threadIdx.x;
    const float* vm = vmean + b * 512;
    float acc = bo[n];
    for (int kk = 0; kk < 512; ++kk)
        acc += vm[kk] * Wo[(size_t)kk*512 + n];
    base[b*512 + n] = acc;
}

__global__ void corr_kernel(const float* __restrict__ upd, const float* __restrict__ vmean,
                            const float* __restrict__ Wo, const int* __restrict__ idx,
                            float* __restrict__ delta) {
    int blk = blockIdx.x;
    int bh = blk / UU, u = blk % UU;
    int h = bh & 7, b = bh >> 3;
    __shared__ float du[64];
    int tid = threadIdx.x;
    if (tid < 64) du[tid] = upd[(size_t)blk*64 + tid] - vmean[bh*64 + tid];
    __syncthreads();
    int l = idx[bh*UU + u];
    float* drow = delta + ((size_t)b*LL + l)*DD;
    const float* wrow = Wo + (size_t)h*64*512;
    #pragma unroll
    for (int half = 0; half < 2; ++half) {
        int n = tid + half*256;
        float acc = 0.f;
        #pragma unroll 8
        for (int d = 0; d < 64; ++d) acc += du[d] * wrow[(size_t)d*512 + n];
        atomicAdd(&drow[n], acc);
    }
}

// ===================== residual + LayerNorm ================================
__global__ void addln_base_kernel(float* h, const float* __restrict__ delta,
                                  const float* __restrict__ base,
                                  const float* __restrict__ g, const float* __restrict__ b) {
    int row = blockIdx.x, tid = threadIdx.x;
    int bb_ = row >> 11;
    float* hr = h + (size_t)row * DD;
    const float* dr = delta + (size_t)row * DD;
    const float* br = base + bb_ * DD;
    __shared__ float rbuf[8];
    __shared__ float sh_mean, sh_var;
    float s0 = hr[tid]       + dr[tid]       + br[tid];
    float s1 = hr[tid + 256] + dr[tid + 256] + br[tid + 256];
    float s = s0 + s1;
    for (int o = 16; o > 0; o >>= 1) s += __shfl_down_sync(0xffffffffu, s, o);
    if ((tid & 31) == 0) rbuf[tid >> 5] = s;
    __syncthreads();
    if (tid == 0) {
        float t = 0.f;
        #pragma unroll
        for (int i = 0; i < 8; ++i) t += rbuf[i];
        sh_mean = t * (1.f / DD);
    }
    __syncthreads();
    float mval = sh_mean;
    float d0 = s0 - mval, d1 = s1 - mval;
    float vv = d0*d0 + d1*d1;
    for (int o = 16; o > 0; o >>= 1) vv += __shfl_down_sync(0xffffffffu, vv, o);
    if ((tid & 31) == 0) rbuf[tid >> 5] = vv;
    __syncthreads();
    if (tid == 0) {
        float t = 0.f;
        #pragma unroll
        for (int i = 0; i < 8; ++i) t += rbuf[i];
        sh_var = t * (1.f / DD);
    }
    __syncthreads();
    float inv = rsqrtf(sh_var + 1e-5f);
    hr[tid]       = d0 * inv * g[tid]       + b[tid];
    hr[tid + 256] = d1 * inv * g[tid + 256] + b[tid + 256];
}

__global__ void addln_kernel(float* h, const float* __restrict__ a,
                             const float* __restrict__ g, const float* __restrict__ b) {
    int row = blockIdx.x, tid = threadIdx.x;
    float* hr = h + (size_t)row * DD;
    const float* ar = a + (size_t)row * DD;
    __shared__ float rbuf[8];
    __shared__ float sh_mean, sh_var;
    float s0 = hr[tid]       + ar[tid];
    float s1 = hr[tid + 256] + ar[tid + 256];
    float s = s0 + s1;
    for (int o = 16; o > 0; o >>= 1) s += __shfl_down_sync(0xffffffffu, s, o);
    if ((tid & 31) == 0) rbuf[tid >> 5] = s;
    __syncthreads();
    if (tid == 0) {
        float t = 0.f;
        #pragma unroll
        for (int i = 0; i < 8; ++i) t += rbuf[i];
        sh_mean = t * (1.f / DD);
    }
    __syncthreads();
    float mval = sh_mean;
    float d0 = s0 - mval, d1 = s1 - mval;
    float vv = d0*d0 + d1*d1;
    for (int o = 16; o > 0; o >>= 1) vv += __shfl_down_sync(0xffffffffu, vv, o);
    if ((tid & 31) == 0) rbuf[tid >> 5] = vv;
    __syncthreads();
    if (tid == 0) {
        float t = 0.f;
        #pragma unroll
        for (int i = 0; i < 8; ++i) t += rbuf[i];
        sh_var = t * (1.f / DD);
    }
    __syncthreads();
    float inv = rsqrtf(sh_var + 1e-5f);
    hr[tid]       = d0 * inv * g[tid]       + b[tid];
    hr[tid + 256] = d1 * inv * g[tid + 256] + b[tid + 256];
}

// ===================== final projection ====================================
__global__ void proj_kernel(const float* __restrict__ h, const float* __restrict__ pw,
                            const float* __restrict__ pb, float* __restrict__ out) {
    int bp = blockIdx.x;
    int b = bp / PP, p = bp % PP;
    int l = LL - PP + p;
    int tid = threadIdx.x;
    const float* hr = h + ((size_t)b*LL + l)*DD;
    float acc[EE];
    #pragma unroll
    for (int e = 0; e < EE; ++e) acc[e] = 0.f;
    for (int kk = tid; kk < DD; kk += 64) {
        float hv = hr[kk];
        #pragma unroll
        for (int e = 0; e < EE; ++e) acc[e] += hv * pw[kk*EE + e];
    }
    __shared__ float red[EE][64];
    #pragma unroll
    for (int e = 0; e < EE; ++e) red[e][tid] = acc[e];
    __syncthreads();
    if (tid < EE) {
        float t = 0.f;
        for (int i = 0; i < 64; ++i) t += red[tid][i];
        out[(size_t)bp * EE + tid] = t + pb[tid];
    }
}

// ===================== host driver =========================================
#define SMEM_G_BYTES (4 * GARR * 2)
#define SMEM_M_BYTES (3*128*MPAD*2 + 1024)
#define SMEM_A_BYTES ((8*2048 + 512 + 2048 + 8) * 4)

extern "C" void kernel_launch(void* const* d_in, const int* in_sizes, int n_in,
                              void* d_out, int out_size) {
    const float* x      = (const float*)d_in[0];
    const float* emb_w  = (const float*)d_in[1];
    const float* emb_b  = (const float*)d_in[2];
    const float* Wq     = (const float*)d_in[3];
    const float* bq     = (const float*)d_in[4];
    const float* Wk     = (const float*)d_in[5];
    const float* bk     = (const float*)d_in[6];
    const float* Wv     = (const float*)d_in[7];
    const float* bv     = (const float*)d_in[8];
    const float* Wo     = (const float*)d_in[9];
    const float* bo     = (const float*)d_in[10];
    const float* W1     = (const float*)d_in[11];
    const float* b1     = (const float*)d_in[12];
    const float* W2     = (const float*)d_in[13];
    const float* b2     = (const float*)d_in[14];
    const float* ln1_g  = (const float*)d_in[15];
    const float* ln1_b  = (const float*)d_in[16];
    const float* ln2_g  = (const float*)d_in[17];
    const float* ln2_b  = (const float*)d_in[18];
    const float* proj_w = (const float*)d_in[19];
    const float* proj_b = (const float*)d_in[20];

    static float *p_h = nullptr, *p_q, *p_k, *p_v, *p_t1, *p_t2, *p_M,
                 *p_ksum, *p_vmean, *p_upd, *p_base;
    static bf16 *p_ah, *p_al, *p_wh, *p_wl, *p_qh, *p_kh;
    static int *p_idx;
    if (!p_h) {
        cudaGetSymbolAddress((void**)&p_h,    g_h);
        cudaGetSymbolAddress((void**)&p_q,    g_q);
        cudaGetSymbolAddress((void**)&p_k,    g_k);
        cudaGetSymbolAddress((void**)&p_v,    g_v);
        cudaGetSymbolAddress((void**)&p_t1,   g_t1);
        cudaGetSymbolAddress((void**)&p_t2,   g_t2);
        cudaGetSymbolAddress((void**)&p_M,    g_M);
        cudaGetSymbolAddress((void**)&p_idx,  g_idx);
        cudaGetSymbolAddress((void**)&p_ksum, g_ksum);
        cudaGetSymbolAddress((void**)&p_vmean,g_vmean);
        cudaGetSymbolAddress((void**)&p_upd,  g_upd);
        cudaGetSymbolAddress((void**)&p_base, g_base);
        cudaGetSymbolAddress((void**)&p_ah,   g_ah);
        cudaGetSymbolAddress((void**)&p_al,   g_al);
        cudaGetSymbolAddress((void**)&p_wh,   g_wh);
        cudaGetSymbolAddress((void**)&p_wl,   g_wl);
        cudaGetSymbolAddress((void**)&p_qh,   g_qh);
        cudaGetSymbolAddress((void**)&p_kh,   g_kh);
        cudaFuncSetAttribute(gemm_mma<0>, cudaFuncAttributeMaxDynamicSharedMemorySize, SMEM_G_BYTES);
        cudaFuncSetAttribute(gemm_mma<1>, cudaFuncAttributeMaxDynamicSharedMemorySize, SMEM_G_BYTES);
        cudaFuncSetAttribute(gemm_mma<2>, cudaFuncAttributeMaxDynamicSharedMemorySize, SMEM_G_BYTES);
        cudaFuncSetAttribute(gemm_mma<3>, cudaFuncAttributeMaxDynamicSharedMemorySize, SMEM_G_BYTES);
        cudaFuncSetAttribute(m_mma,       cudaFuncAttributeMaxDynamicSharedMemorySize, SMEM_M_BYTES);
        cudaFuncSetAttribute(attn_kernel, cudaFuncAttributeMaxDynamicSharedMemorySize, SMEM_A_BYTES);
    }

    embed_kernel<<<(BB*LL*DD)/256, 256>>>(x, emb_w, emb_b, p_h);

    dim3 gg(MROWS/128, DD/128);
    dim3 wsg(16, 16, 5), wsb(32, 8);
    const int NSPLIT = (MROWS*DD/4)/256;
    for (int il = 0; il < NL; ++il) {
        const size_t wo = (size_t)il * DD * DD;
        const size_t boff = (size_t)il * DD;
        wsplit_kernel<<<wsg, wsb>>>(Wq + wo, Wk + wo, Wv + wo, W1 + wo, W2 + wo, p_wh, p_wl);
        split_kernel<<<NSPLIT, 256>>>(p_h, p_ah, p_al);
        gemm_mma<3><<<gg, 256, SMEM_G_BYTES>>>(p_ah, p_al, p_wh + 0*DD*DD, p_wl + 0*DD*DD, bq + boff, p_q, p_qh);
        gemm_mma<3><<<gg, 256, SMEM_G_BYTES>>>(p_ah, p_al, p_wh + 1*DD*DD, p_wl + 1*DD*DD, bk + boff, p_k, p_kh);
        gemm_mma<2><<<gg, 256, SMEM_G_BYTES>>>(p_ah, p_al, p_wh + 2*DD*DD, p_wl + 2*DD*DD, bv + boff, p_v, p_qh);
        sums_kernel<<<BH, 256>>>(p_k, p_v, p_ksum, p_vmean);
        m_mma<<<dim3(LL/128, BH), 256, SMEM_M_BYTES>>>(p_qh, p_kh, p_q, p_ksum, p_M);
        topk_kernel<<<BH, 256>>>(p_M, p_idx);
        attn_kernel<<<dim3(BH, UU/8), 256, SMEM_A_BYTES>>>(p_q, p_k, p_v, p_idx, p_upd);
        base_kernel<<<BB, 512>>>(p_vmean, Wo + wo, bo + boff, p_base);
        cudaMemsetAsync(p_t2, 0, (size_t)BB*LL*DD*sizeof(float));
        corr_kernel<<<BH*UU, 256>>>(p_upd, p_vmean, Wo + wo, p_idx, p_t2);
        addln_base_kernel<<<MROWS, 256>>>(p_h, p_t2, p_base, ln1_g + boff, ln1_b + boff);
        split_kernel<<<NSPLIT, 256>>>(p_h, p_ah, p_al);
        gemm_mma<1><<<gg, 256, SMEM_G_BYTES>>>(p_ah, p_al, p_wh + 3*DD*DD, p_wl + 3*DD*DD, b1 + boff, p_t1, p_qh);
        split_kernel<<<NSPLIT, 256>>>(p_t1, p_ah, p_al);
        gemm_mma<0><<<gg, 256, SMEM_G_BYTES>>>(p_ah, p_al, p_wh + 4*DD*DD, p_wl + 4*DD*DD, b2 + boff, p_t2, p_qh);
        addln_kernel<<<MROWS, 256>>>(p_h, p_t2, ln2_g + boff, ln2_b + boff);
    }

    proj_kernel<<<BB*PP, 64>>>(p_h, proj_w, proj_b, (float*)d_out);
}

// round 14
// speedup vs baseline: 2.4134x; 1.0368x over previous
#include <cuda_runtime.h>
#include <cuda_bf16.h>
#include <math.h>
#include <stdint.h>

#define BB   4
#define LL   2048
#define EE   7
#define DD   512
#define HH   8
#define DH   64
#define PP   720
#define NL   2
#define UU   40
#define BH   (BB*HH)
#define MROWS (BB*LL)
#define SCALE 0.125f

typedef unsigned long long ull;
typedef uint32_t u32;
typedef __nv_bfloat16 bf16;

// ===================== warp-MMA helpers ====================================
__device__ __forceinline__ u32 smem_u32(const void* p) {
    u32 a;
    asm("{ .reg .u64 t; cvta.to.shared.u64 t, %1; cvt.u32.u64 %0, t; }"
        : "=r"(a) : "l"(p));
    return a;
}
__device__ __forceinline__ void cpasync16(u32 dst, const void* src) {
    asm volatile("cp.async.cg.shared.global [%0], [%1], 16;" :: "r"(dst), "l"(src));
}
#define CP_COMMIT() asm volatile("cp.async.commit_group;" ::: "memory")
#define CP_WAIT(n)  asm volatile("cp.async.wait_group %0;" :: "n"(n) : "memory")

#define LDM4(f, addr) \
    asm volatile("ldmatrix.sync.aligned.m8n8.x4.shared.b16 {%0,%1,%2,%3}, [%4];" \
        : "=r"((f)[0]), "=r"((f)[1]), "=r"((f)[2]), "=r"((f)[3]) : "r"(addr))

#define MMA(c, a, b0, b1) \
    asm volatile("mma.sync.aligned.m16n8k16.row.col.f32.bf16.bf16.f32 " \
        "{%0,%1,%2,%3}, {%4,%5,%6,%7}, {%8,%9}, {%0,%1,%2,%3};" \
        : "+f"((c)[0]), "+f"((c)[1]), "+f"((c)[2]), "+f"((c)[3]) \
        : "r"((a)[0]), "r"((a)[1]), "r"((a)[2]), "r"((a)[3]), "r"(b0), "r"(b1))

__device__ __forceinline__ void split1(float v, bf16& h, bf16& l) {
    h = __float2bfloat16(v);
    l = __float2bfloat16(v - __bfloat162float(h));
}

// ===================== scratch =============================================
__device__ float g_h [BB*LL*DD];
__device__ float g_q [BH*LL*DH];
__device__ float g_k [BH*LL*DH];
__device__ float g_v [BH*LL*DH];
__device__ float g_t2[BB*LL*DD];
__device__ float g_M [BH*LL];
__device__ int   g_idx[BH*UU];
__device__ float g_ksum [BH*DH];
__device__ float g_vmean[BH*DH];
__device__ float g_upd[BH*UU*DH];
__device__ float g_base[BB*DD];
__device__ bf16 g_ah[MROWS*DD];
__device__ bf16 g_al[MROWS*DD];
__device__ bf16 g_bh[MROWS*DD];
__device__ bf16 g_bl[MROWS*DD];
__device__ bf16 g_wh[5*DD*DD];
__device__ bf16 g_wl[5*DD*DD];
__device__ bf16 g_qh[BH*LL*DH];
__device__ bf16 g_kh[BH*LL*DH];

// ===================== weight transpose+split ==============================
__global__ void wsplit_kernel(const float* __restrict__ Wq, const float* __restrict__ Wk,
                              const float* __restrict__ Wv, const float* __restrict__ W1,
                              const float* __restrict__ W2,
                              bf16* __restrict__ wh, bf16* __restrict__ wl) {
    int slot = blockIdx.z;
    const float* W = (slot == 0) ? Wq : (slot == 1) ? Wk : (slot == 2) ? Wv
                   : (slot == 3) ? W1 : W2;
    __shared__ float ts[32][33];
    int n0 = blockIdx.x * 32, k0 = blockIdx.y * 32;
    int tx = threadIdx.x, ty = threadIdx.y;      // (32, 8)
    #pragma unroll
    for (int i = 0; i < 4; ++i)
        ts[ty + i*8][tx] = W[(size_t)(k0 + ty + i*8) * 512 + n0 + tx];
    __syncthreads();
    size_t so = (size_t)slot * DD * DD;
    #pragma unroll
    for (int i = 0; i < 4; ++i) {
        float v = ts[tx][ty + i*8];
        bf16 h, l; split1(v, h, l);
        size_t o = so + (size_t)(n0 + ty + i*8) * 512 + k0 + tx;
        wh[o] = h; wl[o] = l;
    }
}

// ===================== embedding (writes h + hi/lo split) ==================
__global__ void embed_kernel(const float* __restrict__ x,
                             const float* __restrict__ w,
                             const float* __restrict__ b,
                             float* __restrict__ out,
                             bf16* __restrict__ hi, bf16* __restrict__ lo) {
    int i = blockIdx.x * 256 + threadIdx.x;
    int row = i >> 9, n = i & 511;
    float acc = b[n];
    #pragma unroll
    for (int e = 0; e < EE; ++e) acc += x[row*EE + e] * w[e*DD + n];
    out[i] = acc;
    bf16 h, l; split1(acc, h, l);
    hi[i] = h; lo[i] = l;
}

// ===================== warp-MMA GEMM [8192,512]x[512,512] ===================
// MODE 0: plain fp32; 2: head scatter; 3: head scatter + bf16-hi;
// MODE 4: relu -> bf16 hi/lo row-major (no fp32 output)
#define GK 32
#define GPAD 40
#define GARR (2*128*GPAD)
template<int MODE>
__global__ __launch_bounds__(256, 2)
void gemm_mma(const bf16* __restrict__ ah, const bf16* __restrict__ al,
              const bf16* __restrict__ wh, const bf16* __restrict__ wl,
              const float* __restrict__ bias, float* __restrict__ out,
              bf16* __restrict__ outh, bf16* __restrict__ outl) {
    extern __shared__ bf16 sm[];
    bf16* pAh = sm;
    bf16* pAl = pAh + GARR;
    bf16* pBh = pAl + GARR;
    bf16* pBl = pBh + GARR;
    const int tid = threadIdx.x, lane = tid & 31, wid = tid >> 5;
    const int wm = wid & 3, wn = wid >> 2;
    const int m0 = blockIdx.x * 128, n0 = blockIdx.y * 128;

    const u32 sAh = smem_u32(pAh), sAl = smem_u32(pAl);
    const u32 sBh = smem_u32(pBh), sBl = smem_u32(pBl);

    float acc[2][8][4];
    #pragma unroll
    for (int a = 0; a < 2; ++a)
        #pragma unroll
        for (int n = 0; n < 8; ++n)
            #pragma unroll
            for (int j = 0; j < 4; ++j) acc[a][n][j] = 0.f;

    auto load_chunk = [&](int c, int buf) {
        int kb = c * GK;
        #pragma unroll
        for (int u = 0; u < 2; ++u) {
            int i = tid + u * 256;
            int r = i >> 2, j = (i & 3) * 8;
            u32 doff = (u32)((buf * 128 * GPAD + r * GPAD + j) * 2);
            cpasync16(sAh + doff, ah + (size_t)(m0 + r) * 512 + kb + j);
            cpasync16(sAl + doff, al + (size_t)(m0 + r) * 512 + kb + j);
            cpasync16(sBh + doff, wh + (size_t)(n0 + r) * 512 + kb + j);
            cpasync16(sBl + doff, wl + (size_t)(n0 + r) * 512 + kb + j);
        }
        CP_COMMIT();
    };

    load_chunk(0, 0);
    for (int c = 0; c < 16; ++c) {
        int buf = c & 1;
        if (c < 15) load_chunk(c + 1, buf ^ 1);
        if (c < 15) CP_WAIT(1); else CP_WAIT(0);
        __syncthreads();
        u32 bofs = (u32)(buf * 128 * GPAD * 2);
        #pragma unroll
        for (int s = 0; s < 2; ++s) {
            int colb = (s * 16 + (lane >> 4) * 8) * 2;
            u32 fa[2][4], fal[2][4];
            #pragma unroll
            for (int a = 0; a < 2; ++a) {
                u32 ro = (u32)((wm * 32 + a * 16 + (lane & 15)) * GPAD * 2) + colb + bofs;
                LDM4(fa[a],  sAh + ro);
                LDM4(fal[a], sAl + ro);
            }
            #pragma unroll
            for (int p = 0; p < 4; ++p) {
                u32 fbh[4], fbl[4];
                u32 ro = (u32)((wn * 64 + p * 16 + (lane & 15)) * GPAD * 2) + colb + bofs;
                LDM4(fbh, sBh + ro);
                LDM4(fbl, sBl + ro);
                #pragma unroll
                for (int a = 0; a < 2; ++a) {
                    MMA(acc[a][2*p],   fa[a],  fbh[0], fbh[2]);
                    MMA(acc[a][2*p+1], fa[a],  fbh[1], fbh[3]);
                    MMA(acc[a][2*p],   fa[a],  fbl[0], fbl[2]);
                    MMA(acc[a][2*p+1], fa[a],  fbl[1], fbl[3]);
                    MMA(acc[a][2*p],   fal[a], fbh[0], fbh[2]);
                    MMA(acc[a][2*p+1], fal[a], fbh[1], fbh[3]);
                }
            }
        }
        __syncthreads();
    }

    int rg = m0 + wm * 32 + (lane >> 2);
    int cg = n0 + wn * 64 + (lane & 3) * 2;
    #pragma unroll
    for (int a = 0; a < 2; ++a)
        #pragma unroll
        for (int n = 0; n < 8; ++n) {
            int col = cg + n * 8;
            float2 bv = *(const float2*)&bias[col];
            #pragma unroll
            for (int hf = 0; hf < 2; ++hf) {
                int row = rg + a * 16 + hf * 8;
                float2 v = make_float2(acc[a][n][hf*2] + bv.x, acc[a][n][hf*2+1] + bv.y);
                if (MODE == 4) {
                    v.x = fmaxf(v.x, 0.f); v.y = fmaxf(v.y, 0.f);
                    bf16 hx, lx, hy, ly;
                    split1(v.x, hx, lx); split1(v.y, hy, ly);
                    __nv_bfloat162 hv = __halves2bfloat162(*(__nv_bfloat16*)&hx, *(__nv_bfloat16*)&hy);
                    __nv_bfloat162 lv = __halves2bfloat162(*(__nv_bfloat16*)&lx, *(__nv_bfloat16*)&ly);
                    size_t o = (size_t)row * 512 + col;
                    *(u32*)&outh[o] = *(u32*)&hv;
                    *(u32*)&outl[o] = *(u32*)&lv;
                } else if (MODE >= 2) {
                    int hh = col >> 6, dh = col & 63, b_ = row >> 11, l_ = row & 2047;
                    size_t o = (((size_t)(b_*HH + hh))*LL + l_)*DH + dh;
                    *(float2*)&out[o] = v;
                    if (MODE == 3) {
                        __nv_bfloat162 hv = __floats2bfloat162_rn(v.x, v.y);
                        *(u32*)&outh[o] = *(u32*)&hv;
                    }
                } else {
                    *(float2*)&out[(size_t)row * 512 + col] = v;
                }
            }
        }
}

// ===================== M(q): 1-term bf16 warp MMA (2 CTA/SM) ===============
#define MPAD 72
__global__ __launch_bounds__(256, 2)
void m_mma(const bf16* __restrict__ qh, const bf16* __restrict__ kh,
           const float* __restrict__ qf, const float* __restrict__ ksum,
           float* __restrict__ Mout) {
    extern __shared__ bf16 sm[];
    bf16* pK = sm;                              // 2 x 128 x MPAD
    float* red = (float*)(pK + 2*128*MPAD);     // [2][128]
    const int tid = threadIdx.x, lane = tid & 31, wid = tid >> 5;
    const int wm = wid & 3, wn = wid >> 2;
    const int bh = blockIdx.y, q0 = blockIdx.x * 128;
    const bf16* qhb = qh + (size_t)bh * LL * DH;
    const bf16* khb = kh + (size_t)bh * LL * DH;
    const u32 sK = smem_u32(pK);
    const u32 sQ = sK + 128 * MPAD * 2;         // Q staged in buffer 1

    auto load_k = [&](int t, int buf) {
        #pragma unroll
        for (int u = 0; u < 4; ++u) {
            int i = tid + u * 256;
            int r = i >> 3, j = (i & 7) * 8;
            cpasync16(sK + (u32)((buf * 128 * MPAD + r * MPAD + j) * 2),
                      khb + (size_t)(t * 128 + r) * 64 + j);
        }
        CP_COMMIT();
    };

    load_k(0, 0);
    #pragma unroll
    for (int u = 0; u < 4; ++u) {
        int i = tid + u * 256;
        int r = i >> 3, j = (i & 7) * 8;
        cpasync16(sQ + (u32)((r * MPAD + j) * 2), qhb + (size_t)(q0 + r) * 64 + j);
    }
    CP_COMMIT();
    CP_WAIT(0);
    __syncthreads();

    // hoist Q fragments from buffer 1, then it becomes a K buffer
    u32 fq[4][2][4];
    #pragma unroll
    for (int s = 0; s < 4; ++s) {
        int colb = (s * 16 + (lane >> 4) * 8) * 2;
        #pragma unroll
        for (int a = 0; a < 2; ++a) {
            u32 ro = (u32)((wm * 32 + a * 16 + (lane & 15)) * MPAD * 2) + colb;
            LDM4(fq[s][a], sQ + ro);
        }
    }
    __syncthreads();

    float rmax[2][2];
    rmax[0][0] = rmax[0][1] = rmax[1][0] = rmax[1][1] = -INFINITY;

    for (int t = 0; t < 16; ++t) {
        int buf = t & 1;
        if (t < 15) load_k(t + 1, buf ^ 1);
        if (t < 15) CP_WAIT(1); else CP_WAIT(0);
        __syncthreads();
        float acc[2][8][4];
        #pragma unroll
        for (int a = 0; a < 2; ++a)
            #pragma unroll
            for (int n = 0; n < 8; ++n)
                #pragma unroll
                for (int j = 0; j < 4; ++j) acc[a][n][j] = 0.f;
        u32 bofs = (u32)(buf * 128 * MPAD * 2);
        #pragma unroll
        for (int s = 0; s < 4; ++s) {
            int colb = (s * 16 + (lane >> 4) * 8) * 2;
            #pragma unroll
            for (int p = 0; p < 4; ++p) {
                u32 fb[4];
                u32 ro = (u32)((wn * 64 + p * 16 + (lane & 15)) * MPAD * 2) + colb + bofs;
                LDM4(fb, sK + ro);
                #pragma unroll
                for (int a = 0; a < 2; ++a) {
                    MMA(acc[a][2*p],   fq[s][a], fb[0], fb[2]);
                    MMA(acc[a][2*p+1], fq[s][a], fb[1], fb[3]);
                }
            }
        }
        #pragma unroll
        for (int a = 0; a < 2; ++a)
            #pragma unroll
            for (int n = 0; n < 8; ++n) {
                rmax[a][0] = fmaxf(rmax[a][0], fmaxf(acc[a][n][0], acc[a][n][1]));
                rmax[a][1] = fmaxf(rmax[a][1], fmaxf(acc[a][n][2], acc[a][n][3]));
            }
        __syncthreads();
    }

    #pragma unroll
    for (int a = 0; a < 2; ++a)
        #pragma unroll
        for (int hf = 0; hf < 2; ++hf) {
            float v = rmax[a][hf];
            v = fmaxf(v, __shfl_xor_sync(0xffffffffu, v, 1));
            v = fmaxf(v, __shfl_xor_sync(0xffffffffu, v, 2));
            rmax[a][hf] = v;
        }
    if ((lane & 3) == 0) {
        #pragma unroll
        for (int a = 0; a < 2; ++a)
            #pragma unroll
            for (int hf = 0; hf < 2; ++hf)
                red[wn * 128 + wm * 32 + a * 16 + hf * 8 + (lane >> 2)] = rmax[a][hf];
    }
    __syncthreads();
    if (tid < 128) {
        float m = fmaxf(red[tid], red[128 + tid]);
        const float* ks = ksum + bh * DH;
        const float* qrow = qf + ((size_t)bh * LL + q0 + tid) * DH;
        float dot = 0.f;
        #pragma unroll
        for (int d = 0; d < 64; ++d) dot += qrow[d] * ks[d];
        Mout[bh * LL + q0 + tid] = (m - dot * (1.f / LL)) * SCALE;
    }
}

// ===================== per-(b,h) sums ======================================
__global__ void sums_kernel(const float* __restrict__ k, const float* __restrict__ v,
                            float* __restrict__ ksum, float* __restrict__ vmean) {
    int bh = blockIdx.x, tid = threadIdx.x;
    int d = tid & 63, c = tid >> 6;
    const float* kb = k + (size_t)bh * LL * DH + d;
    const float* vb = v + (size_t)bh * LL * DH + d;
    float ks = 0.f, vs = 0.f;
    for (int l = c; l < LL; l += 4) { ks += kb[(size_t)l*DH]; vs += vb[(size_t)l*DH]; }
    __shared__ float rk[4][64], rv[4][64];
    rk[c][d] = ks; rv[c][d] = vs;
    __syncthreads();
    if (tid < 64) {
        float a = rk[0][tid] + rk[1][tid] + rk[2][tid] + rk[3][tid];
        float m = rv[0][tid] + rv[1][tid] + rv[2][tid] + rv[3][tid];
        ksum [bh*DH + tid] = a;
        vmean[bh*DH + tid] = m * (1.f / LL);
    }
}

// ===================== top-U selection =====================================
__global__ void topk_kernel(const float* __restrict__ M, int* __restrict__ idxout) {
    int bh = blockIdx.x, tid = threadIdx.x;
    __shared__ float sm[LL];
    __shared__ float bvv[256];
    __shared__ int   bii[256];
    for (int l = tid; l < LL; l += 256) sm[l] = M[bh*LL + l];
    __syncthreads();
    for (int it = 0; it < UU; ++it) {
        float best = -INFINITY; int bidx = LL;
        for (int l = tid; l < LL; l += 256) {
            float v = sm[l];
            if (v > best || (v == best && l < bidx)) { best = v; bidx = l; }
        }
        bvv[tid] = best; bii[tid] = bidx;
        __syncthreads();
        for (int s = 128; s > 0; s >>= 1) {
            if (tid < s) {
                if (bvv[tid+s] > bvv[tid] || (bvv[tid+s] == bvv[tid] && bii[tid+s] < bii[tid])) {
                    bvv[tid] = bvv[tid+s]; bii[tid] = bii[tid+s];
                }
            }
            __syncthreads();
        }
        if (tid == 0) { idxout[bh*UU + it] = bii[0]; sm[bii[0]] = -INFINITY; }
        __syncthreads();
    }
}

// ===================== attention (8 queries / block) =======================
__global__ __launch_bounds__(256, 2)
void attn_kernel(const float* __restrict__ q, const float* __restrict__ k,
                 const float* __restrict__ v, const int* __restrict__ idx,
                 float* __restrict__ upd) {
    extern __shared__ float sbuf[];
    float* sc   = sbuf;
    float* qv   = sbuf + 8*2048;
    float* red  = qv + 512;
    float* sinv = red + 2048;
    int bh = blockIdx.x, u0 = blockIdx.y * 8;
    int tid = threadIdx.x;
    const float* kb = k + (size_t)bh * LL * DH;
    const float* vb = v + (size_t)bh * LL * DH;

    for (int i = tid; i < 8*64; i += 256) {
        int u = i >> 6, d = i & 63;
        int lq = idx[bh*UU + u0 + u];
        qv[i] = q[((size_t)bh*LL + lq)*DH + d];
    }
    __syncthreads();

    for (int l = tid; l < LL; l += 256) {
        const float4* kr = (const float4*)(kb + (size_t)l*DH);
        float acc[8];
        #pragma unroll
        for (int u = 0; u < 8; ++u) acc[u] = 0.f;
        #pragma unroll
        for (int t = 0; t < 16; ++t) {
            float4 kv = kr[t];
            #pragma unroll
            for (int u = 0; u < 8; ++u) {
                float4 qq = *(const float4*)&qv[u*64 + t*4];
                acc[u] += kv.x*qq.x + kv.y*qq.y + kv.z*qq.z + kv.w*qq.w;
            }
        }
        #pragma unroll
        for (int u = 0; u < 8; ++u) sc[u*2048 + l] = acc[u] * SCALE;
    }
    __syncthreads();

    {
        int u = tid >> 5, lane = tid & 31;
        float m = -INFINITY;
        for (int l = lane; l < LL; l += 32) m = fmaxf(m, sc[u*2048 + l]);
        #pragma unroll
        for (int o = 16; o > 0; o >>= 1) m = fmaxf(m, __shfl_xor_sync(0xffffffffu, m, o));
        float s = 0.f;
        for (int l = lane; l < LL; l += 32) {
            float e = __expf(sc[u*2048 + l] - m);
            sc[u*2048 + l] = e; s += e;
        }
        #pragma unroll
        for (int o = 16; o > 0; o >>= 1) s += __shfl_xor_sync(0xffffffffu, s, o);
        if (lane == 0) sinv[u] = 1.f / s;
    }
    __syncthreads();

    int d = tid & 63, lc = tid >> 6;
    float acc[8];
    #pragma unroll
    for (int u = 0; u < 8; ++u) acc[u] = 0.f;
    for (int l = lc; l < LL; l += 4) {
        float vv = vb[(size_t)l*DH + d];
        #pragma unroll
        for (int u = 0; u < 8; ++u) acc[u] += sc[u*2048 + l] * vv;
    }
    #pragma unroll
    for (int u = 0; u < 8; ++u) red[(lc*8 + u)*64 + d] = acc[u];
    __syncthreads();
    if (tid < 64) {
        #pragma unroll
        for (int u = 0; u < 8; ++u) {
            float t = red[u*64 + tid] + red[(8+u)*64 + tid] +
                      red[(16+u)*64 + tid] + red[(24+u)*64 + tid];
            upd[((size_t)bh*UU + u0 + u)*DH + tid] = t * sinv[u];
        }
    }
}

// ===================== Wo via base + sparse corrections ====================
__global__ void base_kernel(const float* __restrict__ vmean, const float* __restrict__ Wo,
                            const float* __restrict__ bo, float* __restrict__ base) {
    int b = blockIdx.x, n = threadIdx.x;
    const float* vm = vmean + b * 512;
    float acc = bo[n];
    for (int kk = 0; kk < 512; ++kk)
        acc += vm[kk] * Wo[(size_t)kk*512 + n];
    base[b*512 + n] = acc;
}

__global__ void corr_kernel(const float* __restrict__ upd, const float* __restrict__ vmean,
                            const float* __restrict__ Wo, const int* __restrict__ idx,
                            float* __restrict__ delta) {
    int blk = blockIdx.x;
    int bh = blk / UU, u = blk % UU;
    int h = bh & 7, b = bh >> 3;
    __shared__ float du[64];
    int tid = threadIdx.x;
    if (tid < 64) du[tid] = upd[(size_t)blk*64 + tid] - vmean[bh*64 + tid];
    __syncthreads();
    int l = idx[bh*UU + u];
    float* drow = delta + ((size_t)b*LL + l)*DD;
    const float* wrow = Wo + (size_t)h*64*512;
    #pragma unroll
    for (int half = 0; half < 2; ++half) {
        int n = tid + half*256;
        float acc = 0.f;
        #pragma unroll 8
        for (int d = 0; d < 64; ++d) acc += du[d] * wrow[(size_t)d*512 + n];
        atomicAdd(&drow[n], acc);
    }
}

// ===================== residual + LayerNorm (fused splits) =================
__global__ void addln_base_kernel(float* h, const float* __restrict__ delta,
                                  const float* __restrict__ base,
                                  const float* __restrict__ g, const float* __restrict__ b,
                                  bf16* __restrict__ sh, bf16* __restrict__ sl) {
    int row = blockIdx.x, tid = threadIdx.x;
    int bb_ = row >> 11;
    float* hr = h + (size_t)row * DD;
    const float* dr = delta + (size_t)row * DD;
    const float* br = base + bb_ * DD;
    __shared__ float rbuf[8];
    __shared__ float sh_mean, sh_var;
    float s0 = hr[tid]       + dr[tid]       + br[tid];
    float s1 = hr[tid + 256] + dr[tid + 256] + br[tid + 256];
    float s = s0 + s1;
    for (int o = 16; o > 0; o >>= 1) s += __shfl_down_sync(0xffffffffu, s, o);
    if ((tid & 31) == 0) rbuf[tid >> 5] = s;
    __syncthreads();
    if (tid == 0) {
        float t = 0.f;
        #pragma unroll
        for (int i = 0; i < 8; ++i) t += rbuf[i];
        sh_mean = t * (1.f / DD);
    }
    __syncthreads();
    float mval = sh_mean;
    float d0 = s0 - mval, d1 = s1 - mval;
    float vv = d0*d0 + d1*d1;
    for (int o = 16; o > 0; o >>= 1) vv += __shfl_down_sync(0xffffffffu, vv, o);
    if ((tid & 31) == 0) rbuf[tid >> 5] = vv;
    __syncthreads();
    if (tid == 0) {
        float t = 0.f;
        #pragma unroll
        for (int i = 0; i < 8; ++i) t += rbuf[i];
        sh_var = t * (1.f / DD);
    }
    __syncthreads();
    float inv = rsqrtf(sh_var + 1e-5f);
    float o0 = d0 * inv * g[tid]       + b[tid];
    float o1 = d1 * inv * g[tid + 256] + b[tid + 256];
    hr[tid] = o0; hr[tid + 256] = o1;
    bf16 hh, ll;
    split1(o0, hh, ll); sh[(size_t)row*DD + tid] = hh;       sl[(size_t)row*DD + tid] = ll;
    split1(o1, hh, ll); sh[(size_t)row*DD + tid + 256] = hh; sl[(size_t)row*DD + tid + 256] = ll;
}

template<int SPLIT>
__global__ void addln_kernel(float* h, const float* __restrict__ a,
                             const float* __restrict__ g, const float* __restrict__ b,
                             bf16* __restrict__ sh, bf16* __restrict__ sl) {
    int row = blockIdx.x, tid = threadIdx.x;
    float* hr = h + (size_t)row * DD;
    const float* ar = a + (size_t)row * DD;
    __shared__ float rbuf[8];
    __shared__ float sh_mean, sh_var;
    float s0 = hr[tid]       + ar[tid];
    float s1 = hr[tid + 256] + ar[tid + 256];
    float s = s0 + s1;
    for (int o = 16; o > 0; o >>= 1) s += __shfl_down_sync(0xffffffffu, s, o);
    if ((tid & 31) == 0) rbuf[tid >> 5] = s;
    __syncthreads();
    if (tid == 0) {
        float t = 0.f;
        #pragma unroll
        for (int i = 0; i < 8; ++i) t += rbuf[i];
        sh_mean = t * (1.f / DD);
    }
    __syncthreads();
    float mval = sh_mean;
    float d0 = s0 - mval, d1 = s1 - mval;
    float vv = d0*d0 + d1*d1;
    for (int o = 16; o > 0; o >>= 1) vv += __shfl_down_sync(0xffffffffu, vv, o);
    if ((tid & 31) == 0) rbuf[tid >> 5] = vv;
    __syncthreads();
    if (tid == 0) {
        float t = 0.f;
        #pragma unroll
        for (int i = 0; i < 8; ++i) t += rbuf[i];
        sh_var = t * (1.f / DD);
    }
    __syncthreads();
    float inv = rsqrtf(sh_var + 1e-5f);
    float o0 = d0 * inv * g[tid]       + b[tid];
    float o1 = d1 * inv * g[tid + 256] + b[tid + 256];
    hr[tid] = o0; hr[tid + 256] = o1;
    if (SPLIT) {
        bf16 hh, ll;
        split1(o0, hh, ll); sh[(size_t)row*DD + tid] = hh;       sl[(size_t)row*DD + tid] = ll;
        split1(o1, hh, ll); sh[(size_t)row*DD + tid + 256] = hh; sl[(size_t)row*DD + tid + 256] = ll;
    }
}

// ===================== final projection ====================================
__global__ void proj_kernel(const float* __restrict__ h, const float* __restrict__ pw,
                            const float* __restrict__ pb, float* __restrict__ out) {
    int bp = blockIdx.x;
    int b = bp / PP, p = bp % PP;
    int l = LL - PP + p;
    int tid = threadIdx.x;
    const float* hr = h + ((size_t)b*LL + l)*DD;
    float acc[EE];
    #pragma unroll
    for (int e = 0; e < EE; ++e) acc[e] = 0.f;
    for (int kk = tid; kk < DD; kk += 64) {
        float hv = hr[kk];
        #pragma unroll
        for (int e = 0; e < EE; ++e) acc[e] += hv * pw[kk*EE + e];
    }
    __shared__ float red[EE][64];
    #pragma unroll
    for (int e = 0; e < EE; ++e) red[e][tid] = acc[e];
    __syncthreads();
    if (tid < EE) {
        float t = 0.f;
        for (int i = 0; i < 64; ++i) t += red[tid][i];
        out[(size_t)bp * EE + tid] = t + pb[tid];
    }
}

// ===================== host driver =========================================
#define SMEM_G_BYTES (4 * GARR * 2)
#define SMEM_M_BYTES (2*128*MPAD*2 + 1024)
#define SMEM_A_BYTES ((8*2048 + 512 + 2048 + 8) * 4)

extern "C" void kernel_launch(void* const* d_in, const int* in_sizes, int n_in,
                              void* d_out, int out_size) {
    const float* x      = (const float*)d_in[0];
    const float* emb_w  = (const float*)d_in[1];
    const float* emb_b  = (const float*)d_in[2];
    const float* Wq     = (const float*)d_in[3];
    const float* bq     = (const float*)d_in[4];
    const float* Wk     = (const float*)d_in[5];
    const float* bk     = (const float*)d_in[6];
    const float* Wv     = (const float*)d_in[7];
    const float* bv     = (const float*)d_in[8];
    const float* Wo     = (const float*)d_in[9];
    const float* bo     = (const float*)d_in[10];
    const float* W1     = (const float*)d_in[11];
    const float* b1     = (const float*)d_in[12];
    const float* W2     = (const float*)d_in[13];
    const float* b2     = (const float*)d_in[14];
    const float* ln1_g  = (const float*)d_in[15];
    const float* ln1_b  = (const float*)d_in[16];
    const float* ln2_g  = (const float*)d_in[17];
    const float* ln2_b  = (const float*)d_in[18];
    const float* proj_w = (const float*)d_in[19];
    const float* proj_b = (const float*)d_in[20];

    static float *p_h = nullptr, *p_q, *p_k, *p_v, *p_t2, *p_M,
                 *p_ksum, *p_vmean, *p_upd, *p_base;
    static bf16 *p_ah, *p_al, *p_bh, *p_bl, *p_wh, *p_wl, *p_qh, *p_kh;
    static int *p_idx;
    if (!p_h) {
        cudaGetSymbolAddress((void**)&p_h,    g_h);
        cudaGetSymbolAddress((void**)&p_q,    g_q);
        cudaGetSymbolAddress((void**)&p_k,    g_k);
        cudaGetSymbolAddress((void**)&p_v,    g_v);
        cudaGetSymbolAddress((void**)&p_t2,   g_t2);
        cudaGetSymbolAddress((void**)&p_M,    g_M);
        cudaGetSymbolAddress((void**)&p_idx,  g_idx);
        cudaGetSymbolAddress((void**)&p_ksum, g_ksum);
        cudaGetSymbolAddress((void**)&p_vmean,g_vmean);
        cudaGetSymbolAddress((void**)&p_upd,  g_upd);
        cudaGetSymbolAddress((void**)&p_base, g_base);
        cudaGetSymbolAddress((void**)&p_ah,   g_ah);
        cudaGetSymbolAddress((void**)&p_al,   g_al);
        cudaGetSymbolAddress((void**)&p_bh,   g_bh);
        cudaGetSymbolAddress((void**)&p_bl,   g_bl);
        cudaGetSymbolAddress((void**)&p_wh,   g_wh);
        cudaGetSymbolAddress((void**)&p_wl,   g_wl);
        cudaGetSymbolAddress((void**)&p_qh,   g_qh);
        cudaGetSymbolAddress((void**)&p_kh,   g_kh);
        cudaFuncSetAttribute(gemm_mma<0>, cudaFuncAttributeMaxDynamicSharedMemorySize, SMEM_G_BYTES);
        cudaFuncSetAttribute(gemm_mma<2>, cudaFuncAttributeMaxDynamicSharedMemorySize, SMEM_G_BYTES);
        cudaFuncSetAttribute(gemm_mma<3>, cudaFuncAttributeMaxDynamicSharedMemorySize, SMEM_G_BYTES);
        cudaFuncSetAttribute(gemm_mma<4>, cudaFuncAttributeMaxDynamicSharedMemorySize, SMEM_G_BYTES);
        cudaFuncSetAttribute(m_mma,       cudaFuncAttributeMaxDynamicSharedMemorySize, SMEM_M_BYTES);
        cudaFuncSetAttribute(attn_kernel, cudaFuncAttributeMaxDynamicSharedMemorySize, SMEM_A_BYTES);
    }

    embed_kernel<<<(BB*LL*DD)/256, 256>>>(x, emb_w, emb_b, p_h, p_ah, p_al);

    dim3 gg(MROWS/128, DD/128);
    dim3 wsg(16, 16, 5), wsb(32, 8);
    for (int il = 0; il < NL; ++il) {
        const size_t wo = (size_t)il * DD * DD;
        const size_t boff = (size_t)il * DD;
        wsplit_kernel<<<wsg, wsb>>>(Wq + wo, Wk + wo, Wv + wo, W1 + wo, W2 + wo, p_wh, p_wl);
        gemm_mma<3><<<gg, 256, SMEM_G_BYTES>>>(p_ah, p_al, p_wh + 0*DD*DD, p_wl + 0*DD*DD, bq + boff, p_q, p_qh, p_qh);
        gemm_mma<3><<<gg, 256, SMEM_G_BYTES>>>(p_ah, p_al, p_wh + 1*DD*DD, p_wl + 1*DD*DD, bk + boff, p_k, p_kh, p_kh);
        gemm_mma<2><<<gg, 256, SMEM_G_BYTES>>>(p_ah, p_al, p_wh + 2*DD*DD, p_wl + 2*DD*DD, bv + boff, p_v, p_qh, p_qh);
        sums_kernel<<<BH, 256>>>(p_k, p_v, p_ksum, p_vmean);
        m_mma<<<dim3(LL/128, BH), 256, SMEM_M_BYTES>>>(p_qh, p_kh, p_q, p_ksum, p_M);
        topk_kernel<<<BH, 256>>>(p_M, p_idx);
        attn_kernel<<<dim3(BH, UU/8), 256, SMEM_A_BYTES>>>(p_q, p_k, p_v, p_idx, p_upd);
        base_kernel<<<BB, 512>>>(p_vmean, Wo + wo, bo + boff, p_base);
        cudaMemsetAsync(p_t2, 0, (size_t)BB*LL*DD*sizeof(float));
        corr_kernel<<<BH*UU, 256>>>(p_upd, p_vmean, Wo + wo, p_idx, p_t2);
        addln_base_kernel<<<MROWS, 256>>>(p_h, p_t2, p_base, ln1_g + boff, ln1_b + boff, p_ah, p_al);
        gemm_mma<4><<<gg, 256, SMEM_G_BYTES>>>(p_ah, p_al, p_wh + 3*DD*DD, p_wl + 3*DD*DD, b1 + boff, p_t2, p_bh, p_bl);
        gemm_mma<0><<<gg, 256, SMEM_G_BYTES>>>(p_bh, p_bl, p_wh + 4*DD*DD, p_wl + 4*DD*DD, b2 + boff, p_t2, p_bh, p_bl);
        if (il < NL - 1)
            addln_kernel<1><<<MROWS, 256>>>(p_h, p_t2, ln2_g + boff, ln2_b + boff, p_ah, p_al);
        else
            addln_kernel<0><<<MROWS, 256>>>(p_h, p_t2, ln2_g + boff, ln2_b + boff, p_ah, p_al);
    }

    proj_kernel<<<BB*PP, 64>>>(p_h, proj_w, proj_b, (float*)d_out);
}